// round 2
// baseline (speedup 1.0000x reference)
#include <cuda_runtime.h>
#include <cuda_bf16.h>
#include <math.h>

// ---------------------------------------------------------------------------
// Model constants
// ---------------------------------------------------------------------------
#define BATCH   8
#define LSEQ    256
#define DM      512      // d_model
#define DI      1024     // d_inner
#define DS      16       // d_state
#define DTR     32       // dt_rank
#define DEPTH   24
#define MROWS   (BATCH*LSEQ)     // 2048

// ---------------------------------------------------------------------------
// Static device scratch (allocation-free rule: __device__ globals)
// ---------------------------------------------------------------------------
__device__ float g_resid [MROWS*DM];
__device__ float g_h     [MROWS*DM];
__device__ float g_x     [MROWS*DM];
__device__ float g_xz    [MROWS*2*DI];
__device__ float g_xc_f  [MROWS*DI];
__device__ float g_xc_b  [MROWS*DI];
__device__ float g_xd_f  [MROWS*64];
__device__ float g_xd_b  [MROWS*64];
__device__ float g_dt_f  [MROWS*DI];
__device__ float g_dt_b  [MROWS*DI];
__device__ float g_y_f   [MROWS*DI];
__device__ float g_y_b   [MROWS*DI];
__device__ float g_col   [1568*4608];   // im2col scratch (also used for patch 2048*768)
__device__ float g_t1    [1568*512];
__device__ float g_p1    [8*64*512];
__device__ float g_t2    [288*512];

// ---------------------------------------------------------------------------
// Generic TN GEMM: C[m,n] = epi( sum_k (A[m,k] (+A2[m,k])) * B[n,k] )
// A row-major (lda), B row-major (ldb) -> "NT" dot-product GEMM.
// Optional split-K over gridDim.z with atomicAdd epilogue (C must be zeroed).
// EPI: 0 = alpha*acc                (linear, split-safe)
//      1 = acc + bias[n]            (bias added only by z==0 when split)
//      2 = softplus(acc + bias[n])  (NEVER split)
//      3 = acc + bias[n] + pos[(m%256)*N+n]  (patch embed)
// ---------------------------------------------------------------------------
template<int BN, int TN, int EPI>
__global__ __launch_bounds__(256)
void gemm_kernel(const float* __restrict__ A, const float* __restrict__ A2, int lda,
                 const float* __restrict__ B, int ldb,
                 float* __restrict__ C, int ldc,
                 int M, int N, int K,
                 const float* __restrict__ bias,
                 const float* __restrict__ pos,
                 float alpha)
{
    constexpr int BM = 128, BK = 8, TM = 8;
    __shared__ __align__(16) float As[BK][BM + 4];
    __shared__ __align__(16) float Bs[BK][BN + 4];

    const int tid = threadIdx.x;
    const int tx  = tid & 15;          // BN/TN == 16 for both configs
    const int ty  = tid >> 4;
    const int m0  = blockIdx.y * BM;
    const int n0  = blockIdx.x * BN;
    const int nz  = gridDim.z;
    const int Kc  = K / nz;
    const int kbeg = blockIdx.z * Kc;
    const int kend = kbeg + Kc;

    const int ar = tid >> 1;           // row within tile for loads
    const int ak = (tid & 1) << 2;     // 0 or 4
    const int am = m0 + ar;
    const bool aok   = (am < M);
    const bool bload = (tid < BN * 2);
    const int  bn    = n0 + ar;
    const bool bok   = bload && (bn < N);

    float acc[TM][TN];
    #pragma unroll
    for (int i = 0; i < TM; i++)
        #pragma unroll
        for (int j = 0; j < TN; j++) acc[i][j] = 0.f;

    for (int k0 = kbeg; k0 < kend; k0 += BK) {
        float4 av = make_float4(0.f, 0.f, 0.f, 0.f);
        if (aok) {
            av = *(const float4*)(A + (size_t)am * lda + k0 + ak);
            if (A2) {
                float4 t = *(const float4*)(A2 + (size_t)am * lda + k0 + ak);
                av.x += t.x; av.y += t.y; av.z += t.z; av.w += t.w;
            }
        }
        As[ak + 0][ar] = av.x; As[ak + 1][ar] = av.y;
        As[ak + 2][ar] = av.z; As[ak + 3][ar] = av.w;
        if (bload) {
            float4 bv = make_float4(0.f, 0.f, 0.f, 0.f);
            if (bok) bv = *(const float4*)(B + (size_t)bn * ldb + k0 + ak);
            Bs[ak + 0][ar] = bv.x; Bs[ak + 1][ar] = bv.y;
            Bs[ak + 2][ar] = bv.z; Bs[ak + 3][ar] = bv.w;
        }
        __syncthreads();

        #pragma unroll
        for (int kk = 0; kk < BK; kk++) {
            float a[TM], bf[TN];
            *(float4*)&a[0] = *(const float4*)&As[kk][ty * TM];
            *(float4*)&a[4] = *(const float4*)&As[kk][ty * TM + 4];
            *(float4*)&bf[0] = *(const float4*)&Bs[kk][tx * TN];
            if (TN == 8) *(float4*)&bf[4] = *(const float4*)&Bs[kk][tx * TN + 4];
            #pragma unroll
            for (int i = 0; i < TM; i++)
                #pragma unroll
                for (int j = 0; j < TN; j++)
                    acc[i][j] += a[i] * bf[j];
        }
        __syncthreads();
    }

    const bool split = (nz > 1);
    const bool first = (blockIdx.z == 0);
    #pragma unroll
    for (int i = 0; i < TM; i++) {
        const int m = m0 + ty * TM + i;
        if (m >= M) continue;
        #pragma unroll
        for (int j = 0; j < TN; j++) {
            const int n = n0 + tx * TN + j;
            if (n >= N) continue;
            float v = acc[i][j];
            if (EPI == 0) {
                v *= alpha;
            } else if (EPI == 1) {
                if (!split || first) v += bias[n];
            } else if (EPI == 2) {
                v += bias[n];
                v = (v > 20.f) ? v : log1pf(__expf(v));
            } else if (EPI == 3) {
                if (!split || first) v += bias[n] + pos[(m & 255) * N + n];
            }
            float* cp = C + (size_t)m * ldc + n;
            if (split) atomicAdd(cp, v);
            else       *cp = v;
        }
    }
}

// ---------------------------------------------------------------------------
// Patch im2col: col[(b,i,j)][(ci,ki,kj)] = x[b][ci][16i+ki][16j+kj]
// ---------------------------------------------------------------------------
__global__ void im2col_patch_kernel(const float* __restrict__ x, float* __restrict__ col)
{
    int id = blockIdx.x * 256 + threadIdx.x;
    if (id >= MROWS * 768) return;
    int k = id % 768;
    int m = id / 768;
    int b = m >> 8, l = m & 255;
    int i = l >> 4, j = l & 15;
    int ci = k >> 8, r = k & 255;
    int ki = r >> 4, kj = r & 15;
    col[id] = x[(((size_t)b * 3 + ci) * 256 + i * 16 + ki) * 256 + j * 16 + kj];
}

// ---------------------------------------------------------------------------
// Fused residual-add + RMSNorm (row = (b,l), width 512)
// resid += xin;  hout = resid * rsqrt(mean(resid^2)+eps) * w
// ---------------------------------------------------------------------------
__global__ __launch_bounds__(256)
void addnorm_kernel(const float* __restrict__ xin, float* __restrict__ resid,
                    float* __restrict__ hout, const float* __restrict__ w)
{
    const int row = blockIdx.x;
    const int tid = threadIdx.x;
    const size_t base = (size_t)row * DM;
    float v0 = resid[base + tid]       + xin[base + tid];
    float v1 = resid[base + 256 + tid] + xin[base + 256 + tid];
    resid[base + tid] = v0;
    resid[base + 256 + tid] = v1;
    float s = v0 * v0 + v1 * v1;
    #pragma unroll
    for (int o = 16; o > 0; o >>= 1) s += __shfl_xor_sync(0xffffffffu, s, o);
    __shared__ float ss[8];
    __shared__ float stot;
    if ((tid & 31) == 0) ss[tid >> 5] = s;
    __syncthreads();
    if (tid == 0) {
        float t = 0.f;
        #pragma unroll
        for (int i = 0; i < 8; i++) t += ss[i];
        stot = t;
    }
    __syncthreads();
    const float rstd = rsqrtf(stot * (1.f / DM) + 1e-5f);
    hout[base + tid]       = v0 * rstd * w[tid];
    hout[base + 256 + tid] = v1 * rstd * w[256 + tid];
}

// ---------------------------------------------------------------------------
// Depthwise causal (y=0) / anti-causal (y=1) conv over L + SiLU.
// Both directions in one launch via blockIdx.y.
// ---------------------------------------------------------------------------
__global__ __launch_bounds__(256)
void dwconv_kernel(const float* __restrict__ xz,
                   const float* __restrict__ w_f, const float* __restrict__ cb_f,
                   const float* __restrict__ w_b, const float* __restrict__ cb_b,
                   float* __restrict__ out_f, float* __restrict__ out_b)
{
    int id = blockIdx.x * 256 + threadIdx.x;
    if (id >= MROWS * DI) return;
    const int dir = blockIdx.y;
    const float* w  = dir ? w_b  : w_f;
    const float* cb = dir ? cb_b : cb_f;
    float* out      = dir ? out_b : out_f;
    int d  = id & (DI - 1);
    int bl = id >> 10;
    int l  = bl & 255, b = bl >> 8;
    float4 wv = *(const float4*)(w + d * 4);
    float acc = cb[d];
    const float* base = xz + ((size_t)b * LSEQ) * (2 * DI) + d;
    if (!dir) {
        if (l >= 3) acc += wv.x * base[(size_t)(l - 3) * 2048];
        if (l >= 2) acc += wv.y * base[(size_t)(l - 2) * 2048];
        if (l >= 1) acc += wv.z * base[(size_t)(l - 1) * 2048];
        acc += wv.w * base[(size_t)l * 2048];
    } else {
        if (l + 3 < 256) acc += wv.x * base[(size_t)(l + 3) * 2048];
        if (l + 2 < 256) acc += wv.y * base[(size_t)(l + 2) * 2048];
        if (l + 1 < 256) acc += wv.z * base[(size_t)(l + 1) * 2048];
        acc += wv.w * base[(size_t)l * 2048];
    }
    out[id] = acc / (1.f + __expf(-acc));
}

// ---------------------------------------------------------------------------
// Selective scan, both directions via blockIdx.z. One thread per (b,d) chain.
// 128 threads/block -> 128 blocks total (better SM coverage for this
// latency-bound kernel). Fast path exploits A_log = log(1..16)
// (runtime-checked per-thread): exp(dt*A_n) = exp(-dt)^n -> 1 MUFU/step.
// ---------------------------------------------------------------------------
__global__ __launch_bounds__(128)
void scan_kernel(const float* __restrict__ dt_f, const float* __restrict__ dt_b,
                 const float* __restrict__ u_f,  const float* __restrict__ u_b,
                 const float* __restrict__ xd_f, const float* __restrict__ xd_b,
                 const float* __restrict__ xz,
                 const float* __restrict__ Alog_f, const float* __restrict__ Alog_b,
                 const float* __restrict__ Dp_f, const float* __restrict__ Dp_b,
                 float* __restrict__ y_f, float* __restrict__ y_b)
{
    const int b = blockIdx.x, chunk = blockIdx.y, dir = blockIdx.z;
    const int tid = threadIdx.x;
    const int d = chunk * 128 + tid;

    const float* dt   = dir ? dt_b   : dt_f;
    const float* u    = dir ? u_b    : u_f;
    const float* xd   = dir ? xd_b   : xd_f;
    const float* Alog = dir ? Alog_b : Alog_f;
    const float* Dp   = dir ? Dp_b   : Dp_f;
    float*       y    = dir ? y_b    : y_f;

    float a[DS];
    bool pw = true;
    #pragma unroll
    for (int n = 0; n < DS; n++) {
        a[n] = -__expf(Alog[(size_t)d * DS + n]);
        pw = pw && (fabsf(a[n] - (float)(n + 1) * a[0]) <= 1e-4f * (float)(n + 1));
    }
    const float Dv = Dp[d];
    float h[DS];
    #pragma unroll
    for (int n = 0; n < DS; n++) h[n] = 0.f;

    __shared__ float sBC[2][32];

    const int l0 = dir ? (LSEQ - 1) : 0;
    size_t bb = (size_t)(b * LSEQ + l0);
    float dtv = dt[bb * DI + d];
    float uv  = u [bb * DI + d];
    float zv  = xz[bb * (2 * DI) + DI + d];
    if (tid < 32) sBC[0][tid] = xd[bb * 64 + 32 + tid];
    __syncthreads();

    for (int t = 0; t < LSEQ; t++) {
        const int cur = t & 1, nxt = cur ^ 1;
        const float dtc = dtv, uc = uv, zc = zv;
        const int l = dir ? (LSEQ - 1 - t) : t;
        if (t < LSEQ - 1) {
            const int l2 = dir ? (LSEQ - 2 - t) : (t + 1);
            bb = (size_t)(b * LSEQ + l2);
            dtv = dt[bb * DI + d];
            uv  = u [bb * DI + d];
            zv  = xz[bb * (2 * DI) + DI + d];
            if (tid < 32) sBC[nxt][tid] = xd[bb * 64 + 32 + tid];
        }
        const float dtu = dtc * uc;
        float yv = 0.f;
        if (pw) {
            const float e = __expf(dtc * a[0]);
            float p = 1.f;
            #pragma unroll
            for (int n = 0; n < DS; n++) {
                p *= e;
                h[n] = p * h[n] + dtu * sBC[cur][n];
                yv += h[n] * sBC[cur][16 + n];
            }
        } else {
            #pragma unroll
            for (int n = 0; n < DS; n++) {
                const float p = __expf(dtc * a[n]);
                h[n] = p * h[n] + dtu * sBC[cur][n];
                yv += h[n] * sBC[cur][16 + n];
            }
        }
        yv = (yv + Dv * uc) * (zc / (1.f + __expf(-zc)));
        y[((size_t)(b * LSEQ + l)) * DI + d] = yv;
        __syncthreads();
    }
}

// ---------------------------------------------------------------------------
// Head im2col (3x3 VALID) from channel-last src [b][H*H][512]
// ---------------------------------------------------------------------------
__global__ void im2col_head_kernel(const float* __restrict__ src, float* __restrict__ col,
                                   int H, int OH)
{
    int id = blockIdx.x * 256 + threadIdx.x;
    const int total = 8 * OH * OH * 4608;
    if (id >= total) return;
    int k = id % 4608;
    int m = id / 4608;
    int x = m % OH;
    int y = (m / OH) % OH;
    int b = m / (OH * OH);
    int ci = k / 9;
    int r = k - ci * 9;
    int dy = r / 3, dx = r - dy * 3;
    col[id] = src[(((size_t)b * H * H) + (y + dy) * H + (x + dx)) * 512 + ci];
}

// ---------------------------------------------------------------------------
// Adaptive avg pool (channel-last). dst[((b*OH+p)*OH+q)*512 + c]
// ---------------------------------------------------------------------------
__global__ void pool_kernel(const float* __restrict__ src, float* __restrict__ dst,
                            int IH, int OH)
{
    int id = blockIdx.x * 256 + threadIdx.x;
    const int total = 8 * OH * OH * 512;
    if (id >= total) return;
    int c = id & 511;
    int m = id >> 9;
    int q = m % OH;
    int p = (m / OH) % OH;
    int b = m / (OH * OH);
    int sp = p * IH / OH, ep = ((p + 1) * IH + OH - 1) / OH;
    int sq = q * IH / OH, eq = ((q + 1) * IH + OH - 1) / OH;
    float s = 0.f;
    for (int y = sp; y < ep; y++)
        for (int x = sq; x < eq; x++)
            s += src[(((size_t)b * IH * IH) + y * IH + x) * 512 + c];
    dst[id] = s / (float)((ep - sp) * (eq - sq));
}

// ---------------------------------------------------------------------------
// Host orchestration
// ---------------------------------------------------------------------------
extern "C" void kernel_launch(void* const* d_in, const int* in_sizes, int n_in,
                              void* d_out, int out_size)
{
    const float* x        = (const float*)d_in[0];
    const float* patch_w  = (const float*)d_in[1];
    const float* patch_b  = (const float*)d_in[2];
    const float* pos      = (const float*)d_in[3];
    const float* norm_w   = (const float*)d_in[4];
    const float* in_w     = (const float*)d_in[5];
    const float* cw_f     = (const float*)d_in[6];
    const float* cb_f     = (const float*)d_in[7];
    const float* xp_f     = (const float*)d_in[8];
    const float* dtw_f    = (const float*)d_in[9];
    const float* dtb_f    = (const float*)d_in[10];
    const float* al_f     = (const float*)d_in[11];
    const float* D_f      = (const float*)d_in[12];
    const float* cw_b     = (const float*)d_in[13];
    const float* cb_b     = (const float*)d_in[14];
    const float* xp_b     = (const float*)d_in[15];
    const float* dtw_b    = (const float*)d_in[16];
    const float* dtb_b    = (const float*)d_in[17];
    const float* al_b     = (const float*)d_in[18];
    const float* D_b      = (const float*)d_in[19];
    const float* out_w    = (const float*)d_in[20];
    const float* norm_fw  = (const float*)d_in[21];
    const float* c1w      = (const float*)d_in[22];
    const float* c1b      = (const float*)d_in[23];
    const float* c2w      = (const float*)d_in[24];
    const float* c2b      = (const float*)d_in[25];
    float* out = (float*)d_out;

    float *resid, *hbuf, *xbuf, *xz, *xcf, *xcb, *xdf, *xdb, *dtf, *dtb_s, *yf, *yb,
          *col, *t1, *p1, *t2;
    cudaGetSymbolAddress((void**)&resid, g_resid);
    cudaGetSymbolAddress((void**)&hbuf,  g_h);
    cudaGetSymbolAddress((void**)&xbuf,  g_x);
    cudaGetSymbolAddress((void**)&xz,    g_xz);
    cudaGetSymbolAddress((void**)&xcf,   g_xc_f);
    cudaGetSymbolAddress((void**)&xcb,   g_xc_b);
    cudaGetSymbolAddress((void**)&xdf,   g_xd_f);
    cudaGetSymbolAddress((void**)&xdb,   g_xd_b);
    cudaGetSymbolAddress((void**)&dtf,   g_dt_f);
    cudaGetSymbolAddress((void**)&dtb_s, g_dt_b);
    cudaGetSymbolAddress((void**)&yf,    g_y_f);
    cudaGetSymbolAddress((void**)&yb,    g_y_b);
    cudaGetSymbolAddress((void**)&col,   g_col);
    cudaGetSymbolAddress((void**)&t1,    g_t1);
    cudaGetSymbolAddress((void**)&p1,    g_p1);
    cudaGetSymbolAddress((void**)&t2,    g_t2);

    // residual starts at zero
    cudaMemsetAsync(resid, 0, (size_t)MROWS * DM * sizeof(float));

    // ---- patch embed: im2col + GEMM (+bias +pos) -> xbuf ----
    {
        int total = MROWS * 768;
        im2col_patch_kernel<<<(total + 255) / 256, 256>>>(x, col);
        gemm_kernel<128, 8, 3><<<dim3(4, 16, 1), 256>>>(
            col, nullptr, 768, patch_w, 768, xbuf, DM,
            MROWS, DM, 768, patch_b, pos, 1.f);
    }

    // ---- 24 Mamba blocks ----
    for (int layer = 0; layer < DEPTH; ++layer) {
        const float* lw_norm = norm_w + (size_t)layer * DM;
        const float* lw_in   = in_w   + (size_t)layer * 2 * DI * DM;
        const float* lw_out  = out_w  + (size_t)layer * DM * DI;

        addnorm_kernel<<<MROWS, 256>>>(xbuf, resid, hbuf, lw_norm);

        // in_proj: xz[2048,2048] = h[2048,512] @ in_w^T
        gemm_kernel<128, 8, 0><<<dim3(16, 16, 1), 256>>>(
            hbuf, nullptr, DM, lw_in, DM, xz, 2 * DI,
            MROWS, 2 * DI, DM, nullptr, nullptr, 1.f);

        // depthwise conv + silu, both directions in one launch
        {
            int total = MROWS * DI;
            dwconv_kernel<<<dim3((total + 255) / 256, 2), 256>>>(
                xz,
                cw_f + (size_t)layer * DI * 4, cb_f + (size_t)layer * DI,
                cw_b + (size_t)layer * DI * 4, cb_b + (size_t)layer * DI,
                xcf, xcb);
        }

        // x_proj: xdbl[2048,64] = xc[2048,1024] @ xp_w^T  (split-K=8, atomic)
        cudaMemsetAsync(xdf, 0, (size_t)MROWS * 64 * sizeof(float));
        cudaMemsetAsync(xdb, 0, (size_t)MROWS * 64 * sizeof(float));
        gemm_kernel<64, 4, 0><<<dim3(1, 16, 8), 256>>>(
            xcf, nullptr, DI, xp_f + (size_t)layer * 64 * DI, DI, xdf, 64,
            MROWS, 64, DI, nullptr, nullptr, 1.f);
        gemm_kernel<64, 4, 0><<<dim3(1, 16, 8), 256>>>(
            xcb, nullptr, DI, xp_b + (size_t)layer * 64 * DI, DI, xdb, 64,
            MROWS, 64, DI, nullptr, nullptr, 1.f);

        // dt: softplus(dt_lo @ dt_w^T + dt_b)  (A = first 32 cols of xdbl, lda=64)
        gemm_kernel<128, 8, 2><<<dim3(8, 16, 1), 256>>>(
            xdf, nullptr, 64, dtw_f + (size_t)layer * DI * DTR, DTR, dtf, DI,
            MROWS, DI, DTR, dtb_f + (size_t)layer * DI, nullptr, 1.f);
        gemm_kernel<128, 8, 2><<<dim3(8, 16, 1), 256>>>(
            xdb, nullptr, 64, dtw_b + (size_t)layer * DI * DTR, DTR, dtb_s, DI,
            MROWS, DI, DTR, dtb_b + (size_t)layer * DI, nullptr, 1.f);

        // selective scan, both directions in one launch, 128 blocks
        scan_kernel<<<dim3(BATCH, 8, 2), 128>>>(
            dtf, dtb_s, xcf, xcb, xdf, xdb, xz,
            al_f + (size_t)layer * DI * DS, al_b + (size_t)layer * DI * DS,
            D_f + (size_t)layer * DI, D_b + (size_t)layer * DI,
            yf, yb);

        // out_proj: xbuf = 0.5 * (yf + yb) @ out_w^T
        gemm_kernel<64, 4, 0><<<dim3(8, 16, 1), 256>>>(
            yf, yb, DI, lw_out, DI, xbuf, DM,
            MROWS, DM, DI, nullptr, nullptr, 0.5f);
    }

    // ---- final norm ----
    addnorm_kernel<<<MROWS, 256>>>(xbuf, resid, hbuf, norm_fw);

    // ---- conv1 3x3 VALID (16x16 -> 14x14), implicit GEMM, split-K=8 ----
    {
        int total = 8 * 14 * 14 * 4608;
        im2col_head_kernel<<<(total + 255) / 256, 256>>>(hbuf, col, 16, 14);
        cudaMemsetAsync(t1, 0, (size_t)1568 * 512 * sizeof(float));
        gemm_kernel<128, 8, 1><<<dim3(4, 13, 8), 256>>>(
            col, nullptr, 4608, c1w, 4608, t1, 512,
            1568, 512, 4608, c1b, nullptr, 1.f);
    }
    // pool 14 -> 8
    {
        int total = 8 * 8 * 8 * 512;
        pool_kernel<<<(total + 255) / 256, 256>>>(t1, p1, 14, 8);
    }
    // ---- conv2 3x3 VALID (8x8 -> 6x6), split-K=16 ----
    {
        int total = 8 * 6 * 6 * 4608;
        im2col_head_kernel<<<(total + 255) / 256, 256>>>(p1, col, 8, 6);
        cudaMemsetAsync(t2, 0, (size_t)288 * 512 * sizeof(float));
        gemm_kernel<128, 8, 1><<<dim3(4, 3, 16), 256>>>(
            col, nullptr, 4608, c2w, 4608, t2, 512,
            288, 512, 4608, c2b, nullptr, 1.f);
    }
    // pool 6 -> 4, writing directly into d_out with (B,16,512) layout
    {
        int total = 8 * 4 * 4 * 512;
        pool_kernel<<<(total + 255) / 256, 256>>>(t2, out, 6, 4);
    }
    (void)in_sizes; (void)n_in; (void)out_size;
}

// round 6
// speedup vs baseline: 1.3265x; 1.3265x over previous
#include <cuda_runtime.h>
#include <cuda_bf16.h>
#include <cstdint>
#include <math.h>

// ---------------------------------------------------------------------------
// Model constants
// ---------------------------------------------------------------------------
#define BATCH   8
#define LSEQ    256
#define DM      512
#define DI      1024
#define DS      16
#define DTR     32
#define DEPTH   24
#define MROWS   (BATCH*LSEQ)     // 2048

typedef __nv_bfloat16 bf16;

// ---------------------------------------------------------------------------
// Static device scratch (allocation-free rule: __device__ globals)
// ---------------------------------------------------------------------------
__device__ float g_resid [MROWS*DM];
__device__ float g_h     [MROWS*DM];
__device__ float g_x     [MROWS*DM];
__device__ float g_xz    [MROWS*2*DI];
__device__ float g_xc_f  [MROWS*DI];
__device__ float g_xc_b  [MROWS*DI];
__device__ float g_xd_f  [MROWS*64];
__device__ float g_xd_b  [MROWS*64];
__device__ float g_dt_f  [MROWS*DI];
__device__ float g_dt_b  [MROWS*DI];
__device__ float g_y_f   [MROWS*DI];
__device__ float g_y_b   [MROWS*DI];
__device__ float g_t1    [1568*512];
__device__ float g_p1    [8*64*512];
__device__ float g_t2    [288*512];

// bf16 hi/lo split buffers (activations)
__device__ __align__(16) bf16 g_hh   [MROWS*DM];
__device__ __align__(16) bf16 g_hl   [MROWS*DM];
__device__ __align__(16) bf16 g_xcfh [MROWS*DI];
__device__ __align__(16) bf16 g_xcfl [MROWS*DI];
__device__ __align__(16) bf16 g_xcbh [MROWS*DI];
__device__ __align__(16) bf16 g_xcbl [MROWS*DI];
__device__ __align__(16) bf16 g_dinfh[MROWS*DTR];
__device__ __align__(16) bf16 g_dinfl[MROWS*DTR];
__device__ __align__(16) bf16 g_dinbh[MROWS*DTR];
__device__ __align__(16) bf16 g_dinbl[MROWS*DTR];
__device__ __align__(16) bf16 g_ych  [MROWS*DI];
__device__ __align__(16) bf16 g_ycl  [MROWS*DI];
__device__ __align__(16) bf16 g_colh [1568*4608];   // also patch col 2048*768
__device__ __align__(16) bf16 g_coll [1568*4608];

// bf16 hi/lo split buffers (weights)
__device__ __align__(16) bf16 g_winh [DEPTH*2*DI*DM];
__device__ __align__(16) bf16 g_winl [DEPTH*2*DI*DM];
__device__ __align__(16) bf16 g_wouth[DEPTH*DM*DI];
__device__ __align__(16) bf16 g_woutl[DEPTH*DM*DI];
__device__ __align__(16) bf16 g_wxpfh[DEPTH*64*DI];
__device__ __align__(16) bf16 g_wxpfl[DEPTH*64*DI];
__device__ __align__(16) bf16 g_wxpbh[DEPTH*64*DI];
__device__ __align__(16) bf16 g_wxpbl[DEPTH*64*DI];
__device__ __align__(16) bf16 g_wdtfh[DEPTH*DI*DTR];
__device__ __align__(16) bf16 g_wdtfl[DEPTH*DI*DTR];
__device__ __align__(16) bf16 g_wdtbh[DEPTH*DI*DTR];
__device__ __align__(16) bf16 g_wdtbl[DEPTH*DI*DTR];
__device__ __align__(16) bf16 g_wpth [DM*768];
__device__ __align__(16) bf16 g_wptl [DM*768];
__device__ __align__(16) bf16 g_wc1h [DM*4608];
__device__ __align__(16) bf16 g_wc1l [DM*4608];
__device__ __align__(16) bf16 g_wc2h [DM*4608];
__device__ __align__(16) bf16 g_wc2l [DM*4608];

__device__ __forceinline__ void bsplit(float v, bf16& h, bf16& l) {
    h = __float2bfloat16(v);
    l = __float2bfloat16(v - __bfloat162float(h));
}

// ---------------------------------------------------------------------------
// mma.sync bf16 GEMM with hi/lo split (3-term compensated product).
// C[m,n] = epi( sum_k A[m,k]*B[n,k] ), A,B given as bf16 hi+lo pairs.
// CTA tile 128(M) x 64(N), BK=32. 8 warps as 4(m) x 2(n); warp tile 32x32
// = 2 x 4 m16n8k16 atoms. Fragments loaded with plain 32-bit LDS using the
// documented PTX lane mapping. Row pitch 40 bf16 -> provably conflict-free.
// EPI: 0 raw, 1 +bias[n], 2 softplus(+bias[n]), 3 +bias[n]+pos[(m%256)*N+n]
// ---------------------------------------------------------------------------
#define MMA_BF16(d, a, b) \
    asm volatile("mma.sync.aligned.m16n8k16.row.col.f32.bf16.bf16.f32 " \
        "{%0,%1,%2,%3},{%4,%5,%6,%7},{%8,%9},{%0,%1,%2,%3};" \
        : "+f"((d)[0]), "+f"((d)[1]), "+f"((d)[2]), "+f"((d)[3]) \
        : "r"((a)[0]), "r"((a)[1]), "r"((a)[2]), "r"((a)[3]), \
          "r"((b)[0]), "r"((b)[1]))

template<int EPI>
__global__ __launch_bounds__(256)
void tgemm_kernel(const bf16* __restrict__ aH, const bf16* __restrict__ aL, int lda,
                  const bf16* __restrict__ bH, const bf16* __restrict__ bL, int ldb,
                  float* __restrict__ C, int ldc, int M, int N, int K,
                  const float* __restrict__ bias, const float* __restrict__ pos)
{
    __shared__ __align__(16) bf16 AsH[128][40];
    __shared__ __align__(16) bf16 AsL[128][40];
    __shared__ __align__(16) bf16 BsH[64][40];
    __shared__ __align__(16) bf16 BsL[64][40];

    const int tid = threadIdx.x, wid = tid >> 5, lid = tid & 31;
    const int wm = wid >> 1, wn = wid & 1;          // 4 x 2 warp grid
    const int g = lid >> 2, t = lid & 3;
    const int m0 = blockIdx.y * 128, n0 = blockIdx.x * 64;

    float acc[2][4][4];
    #pragma unroll
    for (int i = 0; i < 2; i++)
        #pragma unroll
        for (int j = 0; j < 4; j++)
            #pragma unroll
            for (int e = 0; e < 4; e++) acc[i][j][e] = 0.f;

    for (int kc = 0; kc < K; kc += 32) {
        // A tiles: 128 rows x 32 bf16 = 512 uint4 per buffer
        #pragma unroll
        for (int u = tid; u < 512; u += 256) {
            const int row = u >> 2, q = u & 3;
            const int mg = m0 + row;
            uint4 vh = make_uint4(0, 0, 0, 0), vl = vh;
            if (mg < M) {
                vh = *(const uint4*)(aH + (size_t)mg * lda + kc + q * 8);
                vl = *(const uint4*)(aL + (size_t)mg * lda + kc + q * 8);
            }
            *(uint4*)&AsH[row][q * 8] = vh;
            *(uint4*)&AsL[row][q * 8] = vl;
        }
        // B tiles: 64 rows (N always multiple of 64)
        {
            const int row = tid >> 2, q = tid & 3;
            *(uint4*)&BsH[row][q * 8] = *(const uint4*)(bH + (size_t)(n0 + row) * ldb + kc + q * 8);
            *(uint4*)&BsL[row][q * 8] = *(const uint4*)(bL + (size_t)(n0 + row) * ldb + kc + q * 8);
        }
        __syncthreads();

        #pragma unroll
        for (int kk = 0; kk < 32; kk += 16) {
            uint32_t ah[2][4], al[2][4], bh[4][2], bl[4][2];
            #pragma unroll
            for (int i = 0; i < 2; i++) {
                const int r = wm * 32 + i * 16 + g;
                ah[i][0] = *(const uint32_t*)&AsH[r    ][kk + 2 * t];
                ah[i][1] = *(const uint32_t*)&AsH[r + 8][kk + 2 * t];
                ah[i][2] = *(const uint32_t*)&AsH[r    ][kk + 2 * t + 8];
                ah[i][3] = *(const uint32_t*)&AsH[r + 8][kk + 2 * t + 8];
                al[i][0] = *(const uint32_t*)&AsL[r    ][kk + 2 * t];
                al[i][1] = *(const uint32_t*)&AsL[r + 8][kk + 2 * t];
                al[i][2] = *(const uint32_t*)&AsL[r    ][kk + 2 * t + 8];
                al[i][3] = *(const uint32_t*)&AsL[r + 8][kk + 2 * t + 8];
            }
            #pragma unroll
            for (int j = 0; j < 4; j++) {
                const int r = wn * 32 + j * 8 + g;
                bh[j][0] = *(const uint32_t*)&BsH[r][kk + 2 * t];
                bh[j][1] = *(const uint32_t*)&BsH[r][kk + 2 * t + 8];
                bl[j][0] = *(const uint32_t*)&BsL[r][kk + 2 * t];
                bl[j][1] = *(const uint32_t*)&BsL[r][kk + 2 * t + 8];
            }
            #pragma unroll
            for (int i = 0; i < 2; i++)
                #pragma unroll
                for (int j = 0; j < 4; j++) {
                    MMA_BF16(acc[i][j], ah[i], bh[j]);
                    MMA_BF16(acc[i][j], ah[i], bl[j]);
                    MMA_BF16(acc[i][j], al[i], bh[j]);
                }
        }
        __syncthreads();
    }

    // Epilogue: direct register -> gmem (2 consecutive floats per lane pair)
    #pragma unroll
    for (int i = 0; i < 2; i++) {
        const int r0 = m0 + wm * 32 + i * 16 + g;
        #pragma unroll
        for (int j = 0; j < 4; j++) {
            const int c = n0 + wn * 32 + j * 8 + 2 * t;
            #pragma unroll
            for (int half = 0; half < 2; half++) {
                const int m = r0 + half * 8;
                if (m >= M) continue;
                #pragma unroll
                for (int e = 0; e < 2; e++) {
                    const int n = c + e;
                    float v = acc[i][j][half * 2 + e];
                    if (EPI == 1) v += bias[n];
                    else if (EPI == 2) { v += bias[n]; v = (v > 20.f) ? v : log1pf(__expf(v)); }
                    else if (EPI == 3) v += bias[n] + pos[(m & 255) * N + n];
                    C[(size_t)m * ldc + n] = v;
                }
            }
        }
    }
}

// ---------------------------------------------------------------------------
// Elementwise helpers
// ---------------------------------------------------------------------------
__global__ void convert_split_kernel(const float* __restrict__ s,
                                     bf16* __restrict__ dh, bf16* __restrict__ dl, int n)
{
    int i = (blockIdx.x * 256 + threadIdx.x) * 4;
    if (i >= n) return;
    float4 v = *(const float4*)(s + i);
    bsplit(v.x, dh[i + 0], dl[i + 0]);
    bsplit(v.y, dh[i + 1], dl[i + 1]);
    bsplit(v.z, dh[i + 2], dl[i + 2]);
    bsplit(v.w, dh[i + 3], dl[i + 3]);
}

// resid += xin; h = rmsnorm(resid)*w  (fp32 + bf16 split outputs)
__global__ __launch_bounds__(256)
void addnorm_kernel(const float* __restrict__ xin, float* __restrict__ resid,
                    float* __restrict__ hout, bf16* __restrict__ hh, bf16* __restrict__ hl,
                    const float* __restrict__ w)
{
    const int row = blockIdx.x;
    const int tid = threadIdx.x;
    const size_t base = (size_t)row * DM;
    float v0 = resid[base + tid]       + xin[base + tid];
    float v1 = resid[base + 256 + tid] + xin[base + 256 + tid];
    resid[base + tid] = v0;
    resid[base + 256 + tid] = v1;
    float s = v0 * v0 + v1 * v1;
    #pragma unroll
    for (int o = 16; o > 0; o >>= 1) s += __shfl_xor_sync(0xffffffffu, s, o);
    __shared__ float ss[8];
    __shared__ float stot;
    if ((tid & 31) == 0) ss[tid >> 5] = s;
    __syncthreads();
    if (tid == 0) {
        float tsum = 0.f;
        #pragma unroll
        for (int i = 0; i < 8; i++) tsum += ss[i];
        stot = tsum;
    }
    __syncthreads();
    const float rstd = rsqrtf(stot * (1.f / DM) + 1e-5f);
    float h0 = v0 * rstd * w[tid];
    float h1 = v1 * rstd * w[256 + tid];
    hout[base + tid] = h0;
    hout[base + 256 + tid] = h1;
    bsplit(h0, hh[base + tid], hl[base + tid]);
    bsplit(h1, hh[base + 256 + tid], hl[base + 256 + tid]);
}

// depthwise conv + SiLU, both directions; fp32 + bf16 split outputs
__global__ __launch_bounds__(256)
void dwconv_kernel(const float* __restrict__ xz,
                   const float* __restrict__ w_f, const float* __restrict__ cb_f,
                   const float* __restrict__ w_b, const float* __restrict__ cb_b,
                   float* __restrict__ out_f, float* __restrict__ out_b,
                   bf16* __restrict__ ofh, bf16* __restrict__ ofl,
                   bf16* __restrict__ obh, bf16* __restrict__ obl)
{
    int id = blockIdx.x * 256 + threadIdx.x;
    if (id >= MROWS * DI) return;
    const int dir = blockIdx.y;
    const float* w  = dir ? w_b  : w_f;
    const float* cb = dir ? cb_b : cb_f;
    float* out      = dir ? out_b : out_f;
    bf16*  oh       = dir ? obh : ofh;
    bf16*  ol       = dir ? obl : ofl;
    int d  = id & (DI - 1);
    int bl = id >> 10;
    int l  = bl & 255, b = bl >> 8;
    float4 wv = *(const float4*)(w + d * 4);
    float acc = cb[d];
    const float* base = xz + ((size_t)b * LSEQ) * (2 * DI) + d;
    if (!dir) {
        if (l >= 3) acc += wv.x * base[(size_t)(l - 3) * 2048];
        if (l >= 2) acc += wv.y * base[(size_t)(l - 2) * 2048];
        if (l >= 1) acc += wv.z * base[(size_t)(l - 1) * 2048];
        acc += wv.w * base[(size_t)l * 2048];
    } else {
        if (l + 3 < 256) acc += wv.x * base[(size_t)(l + 3) * 2048];
        if (l + 2 < 256) acc += wv.y * base[(size_t)(l + 2) * 2048];
        if (l + 1 < 256) acc += wv.z * base[(size_t)(l + 1) * 2048];
        acc += wv.w * base[(size_t)l * 2048];
    }
    float v = acc / (1.f + __expf(-acc));
    out[id] = v;
    bsplit(v, oh[id], ol[id]);
}

// dt_lo extraction: xd[:, :32] -> bf16 split (both dirs)
__global__ void dtin_kernel(const float* __restrict__ xdf, const float* __restrict__ xdb,
                            bf16* __restrict__ fh, bf16* __restrict__ fl,
                            bf16* __restrict__ bh2, bf16* __restrict__ bl2)
{
    int id = blockIdx.x * 256 + threadIdx.x;
    if (id >= MROWS * DTR) return;
    int row = id >> 5, c = id & 31;
    bsplit(xdf[(size_t)row * 64 + c], fh[id], fl[id]);
    bsplit(xdb[(size_t)row * 64 + c], bh2[id], bl2[id]);
}

// yc = 0.5*(yf+yb) -> bf16 split
__global__ void combine_y_kernel(const float* __restrict__ yf, const float* __restrict__ yb,
                                 bf16* __restrict__ ych, bf16* __restrict__ ycl)
{
    int id = blockIdx.x * 256 + threadIdx.x;
    if (id >= MROWS * DI) return;
    bsplit(0.5f * (yf[id] + yb[id]), ych[id], ycl[id]);
}

// Patch im2col -> bf16 split col matrix [2048 x 768]
__global__ void im2col_patch_kernel(const float* __restrict__ x,
                                    bf16* __restrict__ ch, bf16* __restrict__ cl)
{
    int id = blockIdx.x * 256 + threadIdx.x;
    if (id >= MROWS * 768) return;
    int k = id % 768;
    int m = id / 768;
    int b = m >> 8, l = m & 255;
    int i = l >> 4, j = l & 15;
    int ci = k >> 8, r = k & 255;
    int ki = r >> 4, kj = r & 15;
    float v = x[(((size_t)b * 3 + ci) * 256 + i * 16 + ki) * 256 + j * 16 + kj];
    bsplit(v, ch[id], cl[id]);
}

// Head im2col (3x3 VALID), channel-last fp32 src -> bf16 split col
__global__ void im2col_head_kernel(const float* __restrict__ src,
                                   bf16* __restrict__ ch, bf16* __restrict__ cl,
                                   int H, int OH)
{
    int id = blockIdx.x * 256 + threadIdx.x;
    const int total = 8 * OH * OH * 4608;
    if (id >= total) return;
    int k = id % 4608;
    int m = id / 4608;
    int x = m % OH;
    int y = (m / OH) % OH;
    int b = m / (OH * OH);
    int ci = k / 9;
    int r = k - ci * 9;
    int dy = r / 3, dx = r - dy * 3;
    float v = src[(((size_t)b * H * H) + (y + dy) * H + (x + dx)) * 512 + ci];
    bsplit(v, ch[id], cl[id]);
}

// Selective scan (proven in R2; 128 threads x 128 blocks x 2 dirs)
__global__ __launch_bounds__(128)
void scan_kernel(const float* __restrict__ dt_f, const float* __restrict__ dt_b,
                 const float* __restrict__ u_f,  const float* __restrict__ u_b,
                 const float* __restrict__ xd_f, const float* __restrict__ xd_b,
                 const float* __restrict__ xz,
                 const float* __restrict__ Alog_f, const float* __restrict__ Alog_b,
                 const float* __restrict__ Dp_f, const float* __restrict__ Dp_b,
                 float* __restrict__ y_f, float* __restrict__ y_b)
{
    const int b = blockIdx.x, chunk = blockIdx.y, dir = blockIdx.z;
    const int tid = threadIdx.x;
    const int d = chunk * 128 + tid;

    const float* dt   = dir ? dt_b   : dt_f;
    const float* u    = dir ? u_b    : u_f;
    const float* xd   = dir ? xd_b   : xd_f;
    const float* Alog = dir ? Alog_b : Alog_f;
    const float* Dp   = dir ? Dp_b   : Dp_f;
    float*       y    = dir ? y_b    : y_f;

    float a[DS];
    bool pw = true;
    #pragma unroll
    for (int n = 0; n < DS; n++) {
        a[n] = -__expf(Alog[(size_t)d * DS + n]);
        pw = pw && (fabsf(a[n] - (float)(n + 1) * a[0]) <= 1e-4f * (float)(n + 1));
    }
    const float Dv = Dp[d];
    float h[DS];
    #pragma unroll
    for (int n = 0; n < DS; n++) h[n] = 0.f;

    __shared__ float sBC[2][32];

    const int l0 = dir ? (LSEQ - 1) : 0;
    size_t bb = (size_t)(b * LSEQ + l0);
    float dtv = dt[bb * DI + d];
    float uv  = u [bb * DI + d];
    float zv  = xz[bb * (2 * DI) + DI + d];
    if (tid < 32) sBC[0][tid] = xd[bb * 64 + 32 + tid];
    __syncthreads();

    for (int t = 0; t < LSEQ; t++) {
        const int cur = t & 1, nxt = cur ^ 1;
        const float dtc = dtv, uc = uv, zc = zv;
        const int l = dir ? (LSEQ - 1 - t) : t;
        if (t < LSEQ - 1) {
            const int l2 = dir ? (LSEQ - 2 - t) : (t + 1);
            bb = (size_t)(b * LSEQ + l2);
            dtv = dt[bb * DI + d];
            uv  = u [bb * DI + d];
            zv  = xz[bb * (2 * DI) + DI + d];
            if (tid < 32) sBC[nxt][tid] = xd[bb * 64 + 32 + tid];
        }
        const float dtu = dtc * uc;
        float yv = 0.f;
        if (pw) {
            const float e = __expf(dtc * a[0]);
            float p = 1.f;
            #pragma unroll
            for (int n = 0; n < DS; n++) {
                p *= e;
                h[n] = p * h[n] + dtu * sBC[cur][n];
                yv += h[n] * sBC[cur][16 + n];
            }
        } else {
            #pragma unroll
            for (int n = 0; n < DS; n++) {
                const float p = __expf(dtc * a[n]);
                h[n] = p * h[n] + dtu * sBC[cur][n];
                yv += h[n] * sBC[cur][16 + n];
            }
        }
        yv = (yv + Dv * uc) * (zc / (1.f + __expf(-zc)));
        y[((size_t)(b * LSEQ + l)) * DI + d] = yv;
        __syncthreads();
    }
}

// Adaptive avg pool (channel-last)
__global__ void pool_kernel(const float* __restrict__ src, float* __restrict__ dst,
                            int IH, int OH)
{
    int id = blockIdx.x * 256 + threadIdx.x;
    const int total = 8 * OH * OH * 512;
    if (id >= total) return;
    int c = id & 511;
    int m = id >> 9;
    int q = m % OH;
    int p = (m / OH) % OH;
    int b = m / (OH * OH);
    int sp = p * IH / OH, ep = ((p + 1) * IH + OH - 1) / OH;
    int sq = q * IH / OH, eq = ((q + 1) * IH + OH - 1) / OH;
    float s = 0.f;
    for (int y = sp; y < ep; y++)
        for (int x = sq; x < eq; x++)
            s += src[(((size_t)b * IH * IH) + y * IH + x) * 512 + c];
    dst[id] = s / (float)((ep - sp) * (eq - sq));
}

// ---------------------------------------------------------------------------
// Host orchestration
// ---------------------------------------------------------------------------
extern "C" void kernel_launch(void* const* d_in, const int* in_sizes, int n_in,
                              void* d_out, int out_size)
{
    const float* x        = (const float*)d_in[0];
    const float* patch_w  = (const float*)d_in[1];
    const float* patch_b  = (const float*)d_in[2];
    const float* pos      = (const float*)d_in[3];
    const float* norm_w   = (const float*)d_in[4];
    const float* in_w     = (const float*)d_in[5];
    const float* cw_f     = (const float*)d_in[6];
    const float* cb_f     = (const float*)d_in[7];
    const float* xp_f     = (const float*)d_in[8];
    const float* dtw_f    = (const float*)d_in[9];
    const float* dtb_f    = (const float*)d_in[10];
    const float* al_f     = (const float*)d_in[11];
    const float* D_f      = (const float*)d_in[12];
    const float* cw_b     = (const float*)d_in[13];
    const float* cb_b     = (const float*)d_in[14];
    const float* xp_b     = (const float*)d_in[15];
    const float* dtw_b    = (const float*)d_in[16];
    const float* dtb_b    = (const float*)d_in[17];
    const float* al_b     = (const float*)d_in[18];
    const float* D_b      = (const float*)d_in[19];
    const float* out_w    = (const float*)d_in[20];
    const float* norm_fw  = (const float*)d_in[21];
    const float* c1w      = (const float*)d_in[22];
    const float* c1b      = (const float*)d_in[23];
    const float* c2w      = (const float*)d_in[24];
    const float* c2b      = (const float*)d_in[25];
    float* out = (float*)d_out;

    float *resid, *hbuf, *xbuf, *xz, *xcf, *xcb, *xdf, *xdb, *dtf, *dtbuf, *yf, *yb,
          *t1, *p1, *t2;
    bf16 *hh, *hl, *xcfh, *xcfl, *xcbh, *xcbl, *dinfh, *dinfl, *dinbh, *dinbl,
         *ych, *ycl, *colh, *coll,
         *winh, *winl, *wouth, *woutl, *wxpfh, *wxpfl, *wxpbh, *wxpbl,
         *wdtfh, *wdtfl, *wdtbh, *wdtbl, *wpth, *wptl, *wc1h, *wc1l, *wc2h, *wc2l;

    cudaGetSymbolAddress((void**)&resid, g_resid);
    cudaGetSymbolAddress((void**)&hbuf,  g_h);
    cudaGetSymbolAddress((void**)&xbuf,  g_x);
    cudaGetSymbolAddress((void**)&xz,    g_xz);
    cudaGetSymbolAddress((void**)&xcf,   g_xc_f);
    cudaGetSymbolAddress((void**)&xcb,   g_xc_b);
    cudaGetSymbolAddress((void**)&xdf,   g_xd_f);
    cudaGetSymbolAddress((void**)&xdb,   g_xd_b);
    cudaGetSymbolAddress((void**)&dtf,   g_dt_f);
    cudaGetSymbolAddress((void**)&dtbuf, g_dt_b);
    cudaGetSymbolAddress((void**)&yf,    g_y_f);
    cudaGetSymbolAddress((void**)&yb,    g_y_b);
    cudaGetSymbolAddress((void**)&t1,    g_t1);
    cudaGetSymbolAddress((void**)&p1,    g_p1);
    cudaGetSymbolAddress((void**)&t2,    g_t2);
    cudaGetSymbolAddress((void**)&hh,    g_hh);
    cudaGetSymbolAddress((void**)&hl,    g_hl);
    cudaGetSymbolAddress((void**)&xcfh,  g_xcfh);
    cudaGetSymbolAddress((void**)&xcfl,  g_xcfl);
    cudaGetSymbolAddress((void**)&xcbh,  g_xcbh);
    cudaGetSymbolAddress((void**)&xcbl,  g_xcbl);
    cudaGetSymbolAddress((void**)&dinfh, g_dinfh);
    cudaGetSymbolAddress((void**)&dinfl, g_dinfl);
    cudaGetSymbolAddress((void**)&dinbh, g_dinbh);
    cudaGetSymbolAddress((void**)&dinbl, g_dinbl);
    cudaGetSymbolAddress((void**)&ych,   g_ych);
    cudaGetSymbolAddress((void**)&ycl,   g_ycl);
    cudaGetSymbolAddress((void**)&colh,  g_colh);
    cudaGetSymbolAddress((void**)&coll,  g_coll);
    cudaGetSymbolAddress((void**)&winh,  g_winh);
    cudaGetSymbolAddress((void**)&winl,  g_winl);
    cudaGetSymbolAddress((void**)&wouth, g_wouth);
    cudaGetSymbolAddress((void**)&woutl, g_woutl);
    cudaGetSymbolAddress((void**)&wxpfh, g_wxpfh);
    cudaGetSymbolAddress((void**)&wxpfl, g_wxpfl);
    cudaGetSymbolAddress((void**)&wxpbh, g_wxpbh);
    cudaGetSymbolAddress((void**)&wxpbl, g_wxpbl);
    cudaGetSymbolAddress((void**)&wdtfh, g_wdtfh);
    cudaGetSymbolAddress((void**)&wdtfl, g_wdtfl);
    cudaGetSymbolAddress((void**)&wdtbh, g_wdtbh);
    cudaGetSymbolAddress((void**)&wdtbl, g_wdtbl);
    cudaGetSymbolAddress((void**)&wpth,  g_wpth);
    cudaGetSymbolAddress((void**)&wptl,  g_wptl);
    cudaGetSymbolAddress((void**)&wc1h,  g_wc1h);
    cudaGetSymbolAddress((void**)&wc1l,  g_wc1l);
    cudaGetSymbolAddress((void**)&wc2h,  g_wc2h);
    cudaGetSymbolAddress((void**)&wc2l,  g_wc2l);

    // ---- weight conversions (fp32 -> bf16 hi/lo) ----
    #define CONV(src, dh, dl, n) convert_split_kernel<<<((n)/4 + 255) / 256, 256>>>(src, dh, dl, n)
    CONV(in_w,   winh,  winl,  DEPTH * 2 * DI * DM);
    CONV(out_w,  wouth, woutl, DEPTH * DM * DI);
    CONV(xp_f,   wxpfh, wxpfl, DEPTH * 64 * DI);
    CONV(xp_b,   wxpbh, wxpbl, DEPTH * 64 * DI);
    CONV(dtw_f,  wdtfh, wdtfl, DEPTH * DI * DTR);
    CONV(dtw_b,  wdtbh, wdtbl, DEPTH * DI * DTR);
    CONV(patch_w, wpth, wptl,  DM * 768);
    CONV(c1w,    wc1h,  wc1l,  DM * 4608);
    CONV(c2w,    wc2h,  wc2l,  DM * 4608);
    #undef CONV

    cudaMemsetAsync(resid, 0, (size_t)MROWS * DM * sizeof(float));

    // ---- patch embed: M=2048 N=512 K=768 ----
    {
        int total = MROWS * 768;
        im2col_patch_kernel<<<(total + 255) / 256, 256>>>(x, colh, coll);
        tgemm_kernel<3><<<dim3(8, 16), 256>>>(
            colh, coll, 768, wpth, wptl, 768, xbuf, DM,
            MROWS, DM, 768, patch_b, pos);
    }

    // ---- 24 Mamba blocks ----
    for (int layer = 0; layer < DEPTH; ++layer) {
        addnorm_kernel<<<MROWS, 256>>>(xbuf, resid, hbuf, hh, hl, norm_w + (size_t)layer * DM);

        // in_proj: M=2048 N=2048 K=512
        tgemm_kernel<0><<<dim3(32, 16), 256>>>(
            hh, hl, DM, winh + (size_t)layer * 2 * DI * DM, winl + (size_t)layer * 2 * DI * DM, DM,
            xz, 2 * DI, MROWS, 2 * DI, DM, nullptr, nullptr);

        // depthwise conv + silu (both dirs)
        dwconv_kernel<<<dim3((MROWS * DI + 255) / 256, 2), 256>>>(
            xz, cw_f + (size_t)layer * DI * 4, cb_f + (size_t)layer * DI,
            cw_b + (size_t)layer * DI * 4, cb_b + (size_t)layer * DI,
            xcf, xcb, xcfh, xcfl, xcbh, xcbl);

        // x_proj: M=2048 N=64 K=1024
        tgemm_kernel<0><<<dim3(1, 16), 256>>>(
            xcfh, xcfl, DI, wxpfh + (size_t)layer * 64 * DI, wxpfl + (size_t)layer * 64 * DI, DI,
            xdf, 64, MROWS, 64, DI, nullptr, nullptr);
        tgemm_kernel<0><<<dim3(1, 16), 256>>>(
            xcbh, xcbl, DI, wxpbh + (size_t)layer * 64 * DI, wxpbl + (size_t)layer * 64 * DI, DI,
            xdb, 64, MROWS, 64, DI, nullptr, nullptr);

        // dt_lo -> bf16 split
        dtin_kernel<<<(MROWS * DTR + 255) / 256, 256>>>(xdf, xdb, dinfh, dinfl, dinbh, dinbl);

        // dt = softplus(dt_lo @ dt_w^T + dt_b): M=2048 N=1024 K=32
        tgemm_kernel<2><<<dim3(16, 16), 256>>>(
            dinfh, dinfl, DTR, wdtfh + (size_t)layer * DI * DTR, wdtfl + (size_t)layer * DI * DTR, DTR,
            dtf, DI, MROWS, DI, DTR, dtb_f + (size_t)layer * DI, nullptr);
        tgemm_kernel<2><<<dim3(16, 16), 256>>>(
            dinbh, dinbl, DTR, wdtbh + (size_t)layer * DI * DTR, wdtbl + (size_t)layer * DI * DTR, DTR,
            dtbuf, DI, MROWS, DI, DTR, dtb_b + (size_t)layer * DI, nullptr);

        // selective scan (both dirs)
        scan_kernel<<<dim3(BATCH, 8, 2), 128>>>(
            dtf, dtbuf, xcf, xcb, xdf, xdb, xz,
            al_f + (size_t)layer * DI * DS, al_b + (size_t)layer * DI * DS,
            D_f + (size_t)layer * DI, D_b + (size_t)layer * DI, yf, yb);

        // yc = 0.5*(yf+yb) -> bf16 split
        combine_y_kernel<<<(MROWS * DI + 255) / 256, 256>>>(yf, yb, ych, ycl);

        // out_proj: M=2048 N=512 K=1024
        tgemm_kernel<0><<<dim3(8, 16), 256>>>(
            ych, ycl, DI, wouth + (size_t)layer * DM * DI, woutl + (size_t)layer * DM * DI, DI,
            xbuf, DM, MROWS, DM, DI, nullptr, nullptr);
    }

    // ---- final norm ----
    addnorm_kernel<<<MROWS, 256>>>(xbuf, resid, hbuf, hh, hl, norm_fw);

    // ---- conv1 3x3 VALID (16->14): M=1568 N=512 K=4608 ----
    {
        int total = 8 * 14 * 14 * 4608;
        im2col_head_kernel<<<(total + 255) / 256, 256>>>(hbuf, colh, coll, 16, 14);
        tgemm_kernel<1><<<dim3(8, 13), 256>>>(
            colh, coll, 4608, wc1h, wc1l, 4608, t1, 512,
            1568, 512, 4608, c1b, nullptr);
    }
    pool_kernel<<<(8 * 8 * 8 * 512 + 255) / 256, 256>>>(t1, p1, 14, 8);
    // ---- conv2 3x3 VALID (8->6): M=288 N=512 K=4608 ----
    {
        int total = 8 * 6 * 6 * 4608;
        im2col_head_kernel<<<(total + 255) / 256, 256>>>(p1, colh, coll, 8, 6);
        tgemm_kernel<1><<<dim3(8, 3), 256>>>(
            colh, coll, 4608, wc2h, wc2l, 4608, t2, 512,
            288, 512, 4608, c2b, nullptr);
    }
    pool_kernel<<<(8 * 4 * 4 * 512 + 255) / 256, 256>>>(t2, out, 6, 4);

    (void)in_sizes; (void)n_in; (void)out_size;
}

// round 7
// speedup vs baseline: 1.6588x; 1.2505x over previous
#include <cuda_runtime.h>
#include <cuda_bf16.h>
#include <cstdint>
#include <math.h>

#define BATCH   8
#define LSEQ    256
#define DM      512
#define DI      1024
#define DS      16
#define DTR     32
#define DEPTH   24
#define MROWS   (BATCH*LSEQ)     // 2048

typedef __nv_bfloat16 bf16;

// ---------------------------------------------------------------------------
// Static device scratch
// ---------------------------------------------------------------------------
__device__ float g_resid [MROWS*DM];
__device__ float g_h     [MROWS*DM];
__device__ float g_x     [MROWS*DM];
__device__ float g_xz    [MROWS*2*DI];
__device__ float g_xc_f  [MROWS*DI];
__device__ float g_xc_b  [MROWS*DI];
__device__ float g_xd_f  [MROWS*64];
__device__ float g_xd_b  [MROWS*64];
__device__ float g_dt_f  [MROWS*DI];
__device__ float g_dt_b  [MROWS*DI];
__device__ float g_y_f   [MROWS*DI];
__device__ float g_y_b   [MROWS*DI];
__device__ float g_t1    [1568*512];
__device__ float g_p1    [8*64*512];
__device__ float g_t2    [288*512];

__device__ __align__(16) bf16 g_hh   [MROWS*DM];
__device__ __align__(16) bf16 g_hl   [MROWS*DM];
__device__ __align__(16) bf16 g_xcfh [MROWS*DI];
__device__ __align__(16) bf16 g_xcfl [MROWS*DI];
__device__ __align__(16) bf16 g_xcbh [MROWS*DI];
__device__ __align__(16) bf16 g_xcbl [MROWS*DI];
__device__ __align__(16) bf16 g_dinfh[MROWS*DTR];
__device__ __align__(16) bf16 g_dinfl[MROWS*DTR];
__device__ __align__(16) bf16 g_dinbh[MROWS*DTR];
__device__ __align__(16) bf16 g_dinbl[MROWS*DTR];
__device__ __align__(16) bf16 g_ych  [MROWS*DI];
__device__ __align__(16) bf16 g_ycl  [MROWS*DI];
__device__ __align__(16) bf16 g_colh [1568*4608];
__device__ __align__(16) bf16 g_coll [1568*4608];

__device__ __align__(16) bf16 g_winh [DEPTH*2*DI*DM];
__device__ __align__(16) bf16 g_winl [DEPTH*2*DI*DM];
__device__ __align__(16) bf16 g_wouth[DEPTH*DM*DI];
__device__ __align__(16) bf16 g_woutl[DEPTH*DM*DI];
__device__ __align__(16) bf16 g_wxpfh[DEPTH*64*DI];
__device__ __align__(16) bf16 g_wxpfl[DEPTH*64*DI];
__device__ __align__(16) bf16 g_wxpbh[DEPTH*64*DI];
__device__ __align__(16) bf16 g_wxpbl[DEPTH*64*DI];
__device__ __align__(16) bf16 g_wdtfh[DEPTH*DI*DTR];
__device__ __align__(16) bf16 g_wdtfl[DEPTH*DI*DTR];
__device__ __align__(16) bf16 g_wdtbh[DEPTH*DI*DTR];
__device__ __align__(16) bf16 g_wdtbl[DEPTH*DI*DTR];
__device__ __align__(16) bf16 g_wpth [DM*768];
__device__ __align__(16) bf16 g_wptl [DM*768];
__device__ __align__(16) bf16 g_wc1h [DM*4608];
__device__ __align__(16) bf16 g_wc1l [DM*4608];
__device__ __align__(16) bf16 g_wc2h [DM*4608];
__device__ __align__(16) bf16 g_wc2l [DM*4608];

__device__ __forceinline__ void bsplit(float v, bf16& h, bf16& l) {
    h = __float2bfloat16(v);
    l = __float2bfloat16(v - __bfloat162float(h));
}

// ---------------------------------------------------------------------------
// mma.sync bf16 GEMM, hi/lo 3-term split, with split-K (atomicAdd) and
// dual-direction batching (second pointer set, selected by blockIdx.z/nsplit).
// grid = (Ntiles, Mtiles, ndir*nsplit). K % (32*nsplit) == 0 at all call sites.
// EPI: 0 raw, 1 +bias[n], 2 softplus(+bias[n]) [nsplit==1 only],
//      3 +bias[n]+pos[(m%256)*N+n]
// ---------------------------------------------------------------------------
#define MMA_BF16(d, a, b) \
    asm volatile("mma.sync.aligned.m16n8k16.row.col.f32.bf16.bf16.f32 " \
        "{%0,%1,%2,%3},{%4,%5,%6,%7},{%8,%9},{%0,%1,%2,%3};" \
        : "+f"((d)[0]), "+f"((d)[1]), "+f"((d)[2]), "+f"((d)[3]) \
        : "r"((a)[0]), "r"((a)[1]), "r"((a)[2]), "r"((a)[3]), \
          "r"((b)[0]), "r"((b)[1]))

template<int EPI>
__global__ __launch_bounds__(256)
void tgemm_kernel(const bf16* __restrict__ aH, const bf16* __restrict__ aL, int lda,
                  const bf16* __restrict__ bH, const bf16* __restrict__ bL, int ldb,
                  float* __restrict__ C, int ldc, int M, int N, int K,
                  const float* __restrict__ bias, const float* __restrict__ pos,
                  int nsplit,
                  const bf16* aH2, const bf16* aL2,
                  const bf16* bH2, const bf16* bL2,
                  float* C2, const float* bias2)
{
    __shared__ __align__(16) bf16 AsH[128][40];
    __shared__ __align__(16) bf16 AsL[128][40];
    __shared__ __align__(16) bf16 BsH[64][40];
    __shared__ __align__(16) bf16 BsL[64][40];

    const int split = (int)blockIdx.z % nsplit;
    const int dir   = (int)blockIdx.z / nsplit;
    if (dir) { aH = aH2; aL = aL2; bH = bH2; bL = bL2; C = C2; bias = bias2; }

    const int tid = threadIdx.x, wid = tid >> 5, lid = tid & 31;
    const int wm = wid >> 1, wn = wid & 1;
    const int g = lid >> 2, t = lid & 3;
    const int m0 = blockIdx.y * 128, n0 = blockIdx.x * 64;
    const int Kc = K / nsplit;
    const int kbeg = split * Kc;

    float acc[2][4][4];
    #pragma unroll
    for (int i = 0; i < 2; i++)
        #pragma unroll
        for (int j = 0; j < 4; j++)
            #pragma unroll
            for (int e = 0; e < 4; e++) acc[i][j][e] = 0.f;

    for (int kc = kbeg; kc < kbeg + Kc; kc += 32) {
        #pragma unroll
        for (int u = tid; u < 512; u += 256) {
            const int row = u >> 2, q = u & 3;
            const int mg = m0 + row;
            uint4 vh = make_uint4(0, 0, 0, 0), vl = vh;
            if (mg < M) {
                vh = *(const uint4*)(aH + (size_t)mg * lda + kc + q * 8);
                vl = *(const uint4*)(aL + (size_t)mg * lda + kc + q * 8);
            }
            *(uint4*)&AsH[row][q * 8] = vh;
            *(uint4*)&AsL[row][q * 8] = vl;
        }
        {
            const int row = tid >> 2, q = tid & 3;
            *(uint4*)&BsH[row][q * 8] = *(const uint4*)(bH + (size_t)(n0 + row) * ldb + kc + q * 8);
            *(uint4*)&BsL[row][q * 8] = *(const uint4*)(bL + (size_t)(n0 + row) * ldb + kc + q * 8);
        }
        __syncthreads();

        #pragma unroll
        for (int kk = 0; kk < 32; kk += 16) {
            uint32_t ah[2][4], al[2][4], bh[4][2], bl[4][2];
            #pragma unroll
            for (int i = 0; i < 2; i++) {
                const int r = wm * 32 + i * 16 + g;
                ah[i][0] = *(const uint32_t*)&AsH[r    ][kk + 2 * t];
                ah[i][1] = *(const uint32_t*)&AsH[r + 8][kk + 2 * t];
                ah[i][2] = *(const uint32_t*)&AsH[r    ][kk + 2 * t + 8];
                ah[i][3] = *(const uint32_t*)&AsH[r + 8][kk + 2 * t + 8];
                al[i][0] = *(const uint32_t*)&AsL[r    ][kk + 2 * t];
                al[i][1] = *(const uint32_t*)&AsL[r + 8][kk + 2 * t];
                al[i][2] = *(const uint32_t*)&AsL[r    ][kk + 2 * t + 8];
                al[i][3] = *(const uint32_t*)&AsL[r + 8][kk + 2 * t + 8];
            }
            #pragma unroll
            for (int j = 0; j < 4; j++) {
                const int r = wn * 32 + j * 8 + g;
                bh[j][0] = *(const uint32_t*)&BsH[r][kk + 2 * t];
                bh[j][1] = *(const uint32_t*)&BsH[r][kk + 2 * t + 8];
                bl[j][0] = *(const uint32_t*)&BsL[r][kk + 2 * t];
                bl[j][1] = *(const uint32_t*)&BsL[r][kk + 2 * t + 8];
            }
            #pragma unroll
            for (int i = 0; i < 2; i++)
                #pragma unroll
                for (int j = 0; j < 4; j++) {
                    MMA_BF16(acc[i][j], ah[i], bh[j]);
                    MMA_BF16(acc[i][j], ah[i], bl[j]);
                    MMA_BF16(acc[i][j], al[i], bh[j]);
                }
        }
        __syncthreads();
    }

    const bool dobias = (split == 0);
    #pragma unroll
    for (int i = 0; i < 2; i++) {
        const int r0 = m0 + wm * 32 + i * 16 + g;
        #pragma unroll
        for (int j = 0; j < 4; j++) {
            const int c = n0 + wn * 32 + j * 8 + 2 * t;
            #pragma unroll
            for (int half = 0; half < 2; half++) {
                const int m = r0 + half * 8;
                if (m >= M) continue;
                #pragma unroll
                for (int e = 0; e < 2; e++) {
                    const int n = c + e;
                    float v = acc[i][j][half * 2 + e];
                    if (EPI == 1) { if (dobias) v += bias[n]; }
                    else if (EPI == 2) { v += bias[n]; v = (v > 20.f) ? v : log1pf(__expf(v)); }
                    else if (EPI == 3) { if (dobias) v += bias[n] + pos[(m & 255) * N + n]; }
                    float* cp = C + (size_t)m * ldc + n;
                    if (nsplit > 1) atomicAdd(cp, v);
                    else            *cp = v;
                }
            }
        }
    }
}

// ---------------------------------------------------------------------------
// Elementwise helpers
// ---------------------------------------------------------------------------
__global__ void convert_split_kernel(const float* __restrict__ s,
                                     bf16* __restrict__ dh, bf16* __restrict__ dl, int n)
{
    int i = (blockIdx.x * 256 + threadIdx.x) * 4;
    if (i >= n) return;
    float4 v = *(const float4*)(s + i);
    bsplit(v.x, dh[i + 0], dl[i + 0]);
    bsplit(v.y, dh[i + 1], dl[i + 1]);
    bsplit(v.z, dh[i + 2], dl[i + 2]);
    bsplit(v.w, dh[i + 3], dl[i + 3]);
}

__global__ __launch_bounds__(256)
void addnorm_kernel(const float* __restrict__ xin, float* __restrict__ resid,
                    float* __restrict__ hout, bf16* __restrict__ hh, bf16* __restrict__ hl,
                    const float* __restrict__ w)
{
    const int row = blockIdx.x;
    const int tid = threadIdx.x;
    const size_t base = (size_t)row * DM;
    float v0 = resid[base + tid]       + xin[base + tid];
    float v1 = resid[base + 256 + tid] + xin[base + 256 + tid];
    resid[base + tid] = v0;
    resid[base + 256 + tid] = v1;
    float s = v0 * v0 + v1 * v1;
    #pragma unroll
    for (int o = 16; o > 0; o >>= 1) s += __shfl_xor_sync(0xffffffffu, s, o);
    __shared__ float ss[8];
    __shared__ float stot;
    if ((tid & 31) == 0) ss[tid >> 5] = s;
    __syncthreads();
    if (tid == 0) {
        float tsum = 0.f;
        #pragma unroll
        for (int i = 0; i < 8; i++) tsum += ss[i];
        stot = tsum;
    }
    __syncthreads();
    const float rstd = rsqrtf(stot * (1.f / DM) + 1e-5f);
    float h0 = v0 * rstd * w[tid];
    float h1 = v1 * rstd * w[256 + tid];
    hout[base + tid] = h0;
    hout[base + 256 + tid] = h1;
    bsplit(h0, hh[base + tid], hl[base + tid]);
    bsplit(h1, hh[base + 256 + tid], hl[base + 256 + tid]);
}

__global__ __launch_bounds__(256)
void dwconv_kernel(const float* __restrict__ xz,
                   const float* __restrict__ w_f, const float* __restrict__ cb_f,
                   const float* __restrict__ w_b, const float* __restrict__ cb_b,
                   float* __restrict__ out_f, float* __restrict__ out_b,
                   bf16* __restrict__ ofh, bf16* __restrict__ ofl,
                   bf16* __restrict__ obh, bf16* __restrict__ obl)
{
    int id = blockIdx.x * 256 + threadIdx.x;
    if (id >= MROWS * DI) return;
    const int dir = blockIdx.y;
    const float* w  = dir ? w_b  : w_f;
    const float* cb = dir ? cb_b : cb_f;
    float* out      = dir ? out_b : out_f;
    bf16*  oh       = dir ? obh : ofh;
    bf16*  ol       = dir ? obl : ofl;
    int d  = id & (DI - 1);
    int bl = id >> 10;
    int l  = bl & 255, b = bl >> 8;
    float4 wv = *(const float4*)(w + d * 4);
    float acc = cb[d];
    const float* base = xz + ((size_t)b * LSEQ) * (2 * DI) + d;
    if (!dir) {
        if (l >= 3) acc += wv.x * base[(size_t)(l - 3) * 2048];
        if (l >= 2) acc += wv.y * base[(size_t)(l - 2) * 2048];
        if (l >= 1) acc += wv.z * base[(size_t)(l - 1) * 2048];
        acc += wv.w * base[(size_t)l * 2048];
    } else {
        if (l + 3 < 256) acc += wv.x * base[(size_t)(l + 3) * 2048];
        if (l + 2 < 256) acc += wv.y * base[(size_t)(l + 2) * 2048];
        if (l + 1 < 256) acc += wv.z * base[(size_t)(l + 1) * 2048];
        acc += wv.w * base[(size_t)l * 2048];
    }
    float v = acc / (1.f + __expf(-acc));
    out[id] = v;
    bsplit(v, oh[id], ol[id]);
}

__global__ void dtin_kernel(const float* __restrict__ xdf, const float* __restrict__ xdb,
                            bf16* __restrict__ fh, bf16* __restrict__ fl,
                            bf16* __restrict__ bh2, bf16* __restrict__ bl2)
{
    int id = blockIdx.x * 256 + threadIdx.x;
    if (id >= MROWS * DTR) return;
    int row = id >> 5, c = id & 31;
    bsplit(xdf[(size_t)row * 64 + c], fh[id], fl[id]);
    bsplit(xdb[(size_t)row * 64 + c], bh2[id], bl2[id]);
}

__global__ void combine_y_kernel(const float* __restrict__ yf, const float* __restrict__ yb,
                                 bf16* __restrict__ ych, bf16* __restrict__ ycl)
{
    int id = blockIdx.x * 256 + threadIdx.x;
    if (id >= MROWS * DI) return;
    bsplit(0.5f * (yf[id] + yb[id]), ych[id], ycl[id]);
}

__global__ void im2col_patch_kernel(const float* __restrict__ x,
                                    bf16* __restrict__ ch, bf16* __restrict__ cl)
{
    int id = blockIdx.x * 256 + threadIdx.x;
    if (id >= MROWS * 768) return;
    int k = id % 768;
    int m = id / 768;
    int b = m >> 8, l = m & 255;
    int i = l >> 4, j = l & 15;
    int ci = k >> 8, r = k & 255;
    int ki = r >> 4, kj = r & 15;
    float v = x[(((size_t)b * 3 + ci) * 256 + i * 16 + ki) * 256 + j * 16 + kj];
    bsplit(v, ch[id], cl[id]);
}

__global__ void im2col_head_kernel(const float* __restrict__ src,
                                   bf16* __restrict__ ch, bf16* __restrict__ cl,
                                   int H, int OH)
{
    int id = blockIdx.x * 256 + threadIdx.x;
    const int total = 8 * OH * OH * 4608;
    if (id >= total) return;
    int k = id % 4608;
    int m = id / 4608;
    int x = m % OH;
    int y = (m / OH) % OH;
    int b = m / (OH * OH);
    int ci = k / 9;
    int r = k - ci * 9;
    int dy = r / 3, dx = r - dy * 3;
    float v = src[(((size_t)b * H * H) + (y + dy) * H + (x + dx)) * 512 + ci];
    bsplit(v, ch[id], cl[id]);
}

__global__ __launch_bounds__(128)
void scan_kernel(const float* __restrict__ dt_f, const float* __restrict__ dt_b,
                 const float* __restrict__ u_f,  const float* __restrict__ u_b,
                 const float* __restrict__ xd_f, const float* __restrict__ xd_b,
                 const float* __restrict__ xz,
                 const float* __restrict__ Alog_f, const float* __restrict__ Alog_b,
                 const float* __restrict__ Dp_f, const float* __restrict__ Dp_b,
                 float* __restrict__ y_f, float* __restrict__ y_b)
{
    const int b = blockIdx.x, chunk = blockIdx.y, dir = blockIdx.z;
    const int tid = threadIdx.x;
    const int d = chunk * 128 + tid;

    const float* dt   = dir ? dt_b   : dt_f;
    const float* u    = dir ? u_b    : u_f;
    const float* xd   = dir ? xd_b   : xd_f;
    const float* Alog = dir ? Alog_b : Alog_f;
    const float* Dp   = dir ? Dp_b   : Dp_f;
    float*       y    = dir ? y_b    : y_f;

    float a[DS];
    bool pw = true;
    #pragma unroll
    for (int n = 0; n < DS; n++) {
        a[n] = -__expf(Alog[(size_t)d * DS + n]);
        pw = pw && (fabsf(a[n] - (float)(n + 1) * a[0]) <= 1e-4f * (float)(n + 1));
    }
    const float Dv = Dp[d];
    float h[DS];
    #pragma unroll
    for (int n = 0; n < DS; n++) h[n] = 0.f;

    __shared__ float sBC[2][32];

    const int l0 = dir ? (LSEQ - 1) : 0;
    size_t bb = (size_t)(b * LSEQ + l0);
    float dtv = dt[bb * DI + d];
    float uv  = u [bb * DI + d];
    float zv  = xz[bb * (2 * DI) + DI + d];
    if (tid < 32) sBC[0][tid] = xd[bb * 64 + 32 + tid];
    __syncthreads();

    for (int t = 0; t < LSEQ; t++) {
        const int cur = t & 1, nxt = cur ^ 1;
        const float dtc = dtv, uc = uv, zc = zv;
        const int l = dir ? (LSEQ - 1 - t) : t;
        if (t < LSEQ - 1) {
            const int l2 = dir ? (LSEQ - 2 - t) : (t + 1);
            bb = (size_t)(b * LSEQ + l2);
            dtv = dt[bb * DI + d];
            uv  = u [bb * DI + d];
            zv  = xz[bb * (2 * DI) + DI + d];
            if (tid < 32) sBC[nxt][tid] = xd[bb * 64 + 32 + tid];
        }
        const float dtu = dtc * uc;
        float yv = 0.f;
        if (pw) {
            const float e = __expf(dtc * a[0]);
            float p = 1.f;
            #pragma unroll
            for (int n = 0; n < DS; n++) {
                p *= e;
                h[n] = p * h[n] + dtu * sBC[cur][n];
                yv += h[n] * sBC[cur][16 + n];
            }
        } else {
            #pragma unroll
            for (int n = 0; n < DS; n++) {
                const float p = __expf(dtc * a[n]);
                h[n] = p * h[n] + dtu * sBC[cur][n];
                yv += h[n] * sBC[cur][16 + n];
            }
        }
        yv = (yv + Dv * uc) * (zc / (1.f + __expf(-zc)));
        y[((size_t)(b * LSEQ + l)) * DI + d] = yv;
        __syncthreads();
    }
}

__global__ void pool_kernel(const float* __restrict__ src, float* __restrict__ dst,
                            int IH, int OH)
{
    int id = blockIdx.x * 256 + threadIdx.x;
    const int total = 8 * OH * OH * 512;
    if (id >= total) return;
    int c = id & 511;
    int m = id >> 9;
    int q = m % OH;
    int p = (m / OH) % OH;
    int b = m / (OH * OH);
    int sp = p * IH / OH, ep = ((p + 1) * IH + OH - 1) / OH;
    int sq = q * IH / OH, eq = ((q + 1) * IH + OH - 1) / OH;
    float s = 0.f;
    for (int y = sp; y < ep; y++)
        for (int x = sq; x < eq; x++)
            s += src[(((size_t)b * IH * IH) + y * IH + x) * 512 + c];
    dst[id] = s / (float)((ep - sp) * (eq - sq));
}

// ---------------------------------------------------------------------------
// Host orchestration
// ---------------------------------------------------------------------------
extern "C" void kernel_launch(void* const* d_in, const int* in_sizes, int n_in,
                              void* d_out, int out_size)
{
    const float* x        = (const float*)d_in[0];
    const float* patch_w  = (const float*)d_in[1];
    const float* patch_b  = (const float*)d_in[2];
    const float* pos      = (const float*)d_in[3];
    const float* norm_w   = (const float*)d_in[4];
    const float* in_w     = (const float*)d_in[5];
    const float* cw_f     = (const float*)d_in[6];
    const float* cb_f     = (const float*)d_in[7];
    const float* xp_f     = (const float*)d_in[8];
    const float* dtw_f    = (const float*)d_in[9];
    const float* dtb_f    = (const float*)d_in[10];
    const float* al_f     = (const float*)d_in[11];
    const float* D_f      = (const float*)d_in[12];
    const float* cw_b     = (const float*)d_in[13];
    const float* cb_b     = (const float*)d_in[14];
    const float* xp_b     = (const float*)d_in[15];
    const float* dtw_b    = (const float*)d_in[16];
    const float* dtb_b    = (const float*)d_in[17];
    const float* al_b     = (const float*)d_in[18];
    const float* D_b      = (const float*)d_in[19];
    const float* out_w    = (const float*)d_in[20];
    const float* norm_fw  = (const float*)d_in[21];
    const float* c1w      = (const float*)d_in[22];
    const float* c1b      = (const float*)d_in[23];
    const float* c2w      = (const float*)d_in[24];
    const float* c2b      = (const float*)d_in[25];
    float* out = (float*)d_out;

    float *resid, *hbuf, *xbuf, *xz, *xcf, *xcb, *xdf, *xdb, *dtf, *dtbuf, *yf, *yb,
          *t1, *p1, *t2;
    bf16 *hh, *hl, *xcfh, *xcfl, *xcbh, *xcbl, *dinfh, *dinfl, *dinbh, *dinbl,
         *ych, *ycl, *colh, *coll,
         *winh, *winl, *wouth, *woutl, *wxpfh, *wxpfl, *wxpbh, *wxpbl,
         *wdtfh, *wdtfl, *wdtbh, *wdtbl, *wpth, *wptl, *wc1h, *wc1l, *wc2h, *wc2l;

    cudaGetSymbolAddress((void**)&resid, g_resid);
    cudaGetSymbolAddress((void**)&hbuf,  g_h);
    cudaGetSymbolAddress((void**)&xbuf,  g_x);
    cudaGetSymbolAddress((void**)&xz,    g_xz);
    cudaGetSymbolAddress((void**)&xcf,   g_xc_f);
    cudaGetSymbolAddress((void**)&xcb,   g_xc_b);
    cudaGetSymbolAddress((void**)&xdf,   g_xd_f);
    cudaGetSymbolAddress((void**)&xdb,   g_xd_b);
    cudaGetSymbolAddress((void**)&dtf,   g_dt_f);
    cudaGetSymbolAddress((void**)&dtbuf, g_dt_b);
    cudaGetSymbolAddress((void**)&yf,    g_y_f);
    cudaGetSymbolAddress((void**)&yb,    g_y_b);
    cudaGetSymbolAddress((void**)&t1,    g_t1);
    cudaGetSymbolAddress((void**)&p1,    g_p1);
    cudaGetSymbolAddress((void**)&t2,    g_t2);
    cudaGetSymbolAddress((void**)&hh,    g_hh);
    cudaGetSymbolAddress((void**)&hl,    g_hl);
    cudaGetSymbolAddress((void**)&xcfh,  g_xcfh);
    cudaGetSymbolAddress((void**)&xcfl,  g_xcfl);
    cudaGetSymbolAddress((void**)&xcbh,  g_xcbh);
    cudaGetSymbolAddress((void**)&xcbl,  g_xcbl);
    cudaGetSymbolAddress((void**)&dinfh, g_dinfh);
    cudaGetSymbolAddress((void**)&dinfl, g_dinfl);
    cudaGetSymbolAddress((void**)&dinbh, g_dinbh);
    cudaGetSymbolAddress((void**)&dinbl, g_dinbl);
    cudaGetSymbolAddress((void**)&ych,   g_ych);
    cudaGetSymbolAddress((void**)&ycl,   g_ycl);
    cudaGetSymbolAddress((void**)&colh,  g_colh);
    cudaGetSymbolAddress((void**)&coll,  g_coll);
    cudaGetSymbolAddress((void**)&winh,  g_winh);
    cudaGetSymbolAddress((void**)&winl,  g_winl);
    cudaGetSymbolAddress((void**)&wouth, g_wouth);
    cudaGetSymbolAddress((void**)&woutl, g_woutl);
    cudaGetSymbolAddress((void**)&wxpfh, g_wxpfh);
    cudaGetSymbolAddress((void**)&wxpfl, g_wxpfl);
    cudaGetSymbolAddress((void**)&wxpbh, g_wxpbh);
    cudaGetSymbolAddress((void**)&wxpbl, g_wxpbl);
    cudaGetSymbolAddress((void**)&wdtfh, g_wdtfh);
    cudaGetSymbolAddress((void**)&wdtfl, g_wdtfl);
    cudaGetSymbolAddress((void**)&wdtbh, g_wdtbh);
    cudaGetSymbolAddress((void**)&wdtbl, g_wdtbl);
    cudaGetSymbolAddress((void**)&wpth,  g_wpth);
    cudaGetSymbolAddress((void**)&wptl,  g_wptl);
    cudaGetSymbolAddress((void**)&wc1h,  g_wc1h);
    cudaGetSymbolAddress((void**)&wc1l,  g_wc1l);
    cudaGetSymbolAddress((void**)&wc2h,  g_wc2h);
    cudaGetSymbolAddress((void**)&wc2l,  g_wc2l);

    #define CONV(src, dh, dl, n) convert_split_kernel<<<((n)/4 + 255) / 256, 256>>>(src, dh, dl, n)
    CONV(in_w,   winh,  winl,  DEPTH * 2 * DI * DM);
    CONV(out_w,  wouth, woutl, DEPTH * DM * DI);
    CONV(xp_f,   wxpfh, wxpfl, DEPTH * 64 * DI);
    CONV(xp_b,   wxpbh, wxpbl, DEPTH * 64 * DI);
    CONV(dtw_f,  wdtfh, wdtfl, DEPTH * DI * DTR);
    CONV(dtw_b,  wdtbh, wdtbl, DEPTH * DI * DTR);
    CONV(patch_w, wpth, wptl,  DM * 768);
    CONV(c1w,    wc1h,  wc1l,  DM * 4608);
    CONV(c2w,    wc2h,  wc2l,  DM * 4608);
    #undef CONV

    cudaMemsetAsync(resid, 0, (size_t)MROWS * DM * sizeof(float));

    // ---- patch embed: M=2048 N=512 K=768 ----
    {
        int total = MROWS * 768;
        im2col_patch_kernel<<<(total + 255) / 256, 256>>>(x, colh, coll);
        tgemm_kernel<3><<<dim3(8, 16, 1), 256>>>(
            colh, coll, 768, wpth, wptl, 768, xbuf, DM,
            MROWS, DM, 768, patch_b, pos, 1,
            nullptr, nullptr, nullptr, nullptr, nullptr, nullptr);
    }

    // ---- 24 Mamba blocks ----
    for (int layer = 0; layer < DEPTH; ++layer) {
        addnorm_kernel<<<MROWS, 256>>>(xbuf, resid, hbuf, hh, hl, norm_w + (size_t)layer * DM);

        // in_proj: M=2048 N=2048 K=512 (512 CTAs)
        tgemm_kernel<0><<<dim3(32, 16, 1), 256>>>(
            hh, hl, DM, winh + (size_t)layer * 2 * DI * DM, winl + (size_t)layer * 2 * DI * DM, DM,
            xz, 2 * DI, MROWS, 2 * DI, DM, nullptr, nullptr, 1,
            nullptr, nullptr, nullptr, nullptr, nullptr, nullptr);

        // depthwise conv + silu (both dirs)
        dwconv_kernel<<<dim3((MROWS * DI + 255) / 256, 2), 256>>>(
            xz, cw_f + (size_t)layer * DI * 4, cb_f + (size_t)layer * DI,
            cw_b + (size_t)layer * DI * 4, cb_b + (size_t)layer * DI,
            xcf, xcb, xcfh, xcfl, xcbh, xcbl);

        // x_proj both dirs, split-K=4: grid (1,16, 2*4) = 128 CTAs
        cudaMemsetAsync(xdf, 0, (size_t)MROWS * 64 * sizeof(float));
        cudaMemsetAsync(xdb, 0, (size_t)MROWS * 64 * sizeof(float));
        tgemm_kernel<0><<<dim3(1, 16, 8), 256>>>(
            xcfh, xcfl, DI, wxpfh + (size_t)layer * 64 * DI, wxpfl + (size_t)layer * 64 * DI, DI,
            xdf, 64, MROWS, 64, DI, nullptr, nullptr, 4,
            xcbh, xcbl, wxpbh + (size_t)layer * 64 * DI, wxpbl + (size_t)layer * 64 * DI,
            xdb, nullptr);

        // dt_lo -> bf16 split
        dtin_kernel<<<(MROWS * DTR + 255) / 256, 256>>>(xdf, xdb, dinfh, dinfl, dinbh, dinbl);

        // dt both dirs in one launch: grid (16,16,2) = 512 CTAs
        tgemm_kernel<2><<<dim3(16, 16, 2), 256>>>(
            dinfh, dinfl, DTR, wdtfh + (size_t)layer * DI * DTR, wdtfl + (size_t)layer * DI * DTR, DTR,
            dtf, DI, MROWS, DI, DTR, dtb_f + (size_t)layer * DI, nullptr, 1,
            dinbh, dinbl, wdtbh + (size_t)layer * DI * DTR, wdtbl + (size_t)layer * DI * DTR,
            dtbuf, dtb_b + (size_t)layer * DI);

        // selective scan (both dirs)
        scan_kernel<<<dim3(BATCH, 8, 2), 128>>>(
            dtf, dtbuf, xcf, xcb, xdf, xdb, xz,
            al_f + (size_t)layer * DI * DS, al_b + (size_t)layer * DI * DS,
            D_f + (size_t)layer * DI, D_b + (size_t)layer * DI, yf, yb);

        // yc = 0.5*(yf+yb) -> bf16 split
        combine_y_kernel<<<(MROWS * DI + 255) / 256, 256>>>(yf, yb, ych, ycl);

        // out_proj split-K=2: grid (8,16,2) = 256 CTAs
        cudaMemsetAsync(xbuf, 0, (size_t)MROWS * DM * sizeof(float));
        tgemm_kernel<0><<<dim3(8, 16, 2), 256>>>(
            ych, ycl, DI, wouth + (size_t)layer * DM * DI, woutl + (size_t)layer * DM * DI, DI,
            xbuf, DM, MROWS, DM, DI, nullptr, nullptr, 2,
            nullptr, nullptr, nullptr, nullptr, nullptr, nullptr);
    }

    // ---- final norm ----
    addnorm_kernel<<<MROWS, 256>>>(xbuf, resid, hbuf, hh, hl, norm_fw);

    // ---- conv1 (16->14): split-K=4, grid (8,13,4) = 416 CTAs ----
    {
        int total = 8 * 14 * 14 * 4608;
        im2col_head_kernel<<<(total + 255) / 256, 256>>>(hbuf, colh, coll, 16, 14);
        cudaMemsetAsync(t1, 0, (size_t)1568 * 512 * sizeof(float));
        tgemm_kernel<1><<<dim3(8, 13, 4), 256>>>(
            colh, coll, 4608, wc1h, wc1l, 4608, t1, 512,
            1568, 512, 4608, c1b, nullptr, 4,
            nullptr, nullptr, nullptr, nullptr, nullptr, nullptr);
    }
    pool_kernel<<<(8 * 8 * 8 * 512 + 255) / 256, 256>>>(t1, p1, 14, 8);
    // ---- conv2 (8->6): split-K=8, grid (8,3,8) = 192 CTAs ----
    {
        int total = 8 * 6 * 6 * 4608;
        im2col_head_kernel<<<(total + 255) / 256, 256>>>(p1, colh, coll, 8, 6);
        cudaMemsetAsync(t2, 0, (size_t)288 * 512 * sizeof(float));
        tgemm_kernel<1><<<dim3(8, 3, 8), 256>>>(
            colh, coll, 4608, wc2h, wc2l, 4608, t2, 512,
            288, 512, 4608, c2b, nullptr, 8,
            nullptr, nullptr, nullptr, nullptr, nullptr, nullptr);
    }
    pool_kernel<<<(8 * 4 * 4 * 512 + 255) / 256, 256>>>(t2, out, 6, 4);

    (void)in_sizes; (void)n_in; (void)out_size;
}

// round 8
// speedup vs baseline: 1.7497x; 1.0548x over previous
#include <cuda_runtime.h>
#include <cuda_bf16.h>
#include <cstdint>
#include <math.h>

#define BATCH   8
#define LSEQ    256
#define DM      512
#define DI      1024
#define DS      16
#define DTR     32
#define DEPTH   24
#define MROWS   (BATCH*LSEQ)     // 2048

typedef __nv_bfloat16 bf16;

// ---------------------------------------------------------------------------
// Static device scratch
// ---------------------------------------------------------------------------
__device__ float g_resid [MROWS*DM];
__device__ float g_h     [MROWS*DM];
__device__ float g_x     [MROWS*DM];
__device__ float g_xz    [MROWS*2*DI];
__device__ float g_xc_f  [MROWS*DI];
__device__ float g_xc_b  [MROWS*DI];
__device__ float g_xd    [MROWS*128];      // xdf = first half, xdb = second half
__device__ float g_dt_f  [MROWS*DI];
__device__ float g_dt_b  [MROWS*DI];
__device__ float g_y_f   [MROWS*DI];
__device__ float g_y_b   [MROWS*DI];
__device__ float g_colf  [1568*4608];      // fp32 im2col (patch + head)
__device__ float g_t1    [1568*512];
__device__ float g_p1    [8*64*512];
__device__ float g_t2    [288*512];

// bf16 hi/lo weights (converted once per run)
__device__ __align__(16) bf16 g_winh [DEPTH*2*DI*DM];
__device__ __align__(16) bf16 g_winl [DEPTH*2*DI*DM];
__device__ __align__(16) bf16 g_wouth[DEPTH*DM*DI];
__device__ __align__(16) bf16 g_woutl[DEPTH*DM*DI];
__device__ __align__(16) bf16 g_wxpfh[DEPTH*64*DI];
__device__ __align__(16) bf16 g_wxpfl[DEPTH*64*DI];
__device__ __align__(16) bf16 g_wxpbh[DEPTH*64*DI];
__device__ __align__(16) bf16 g_wxpbl[DEPTH*64*DI];
__device__ __align__(16) bf16 g_wdtfh[DEPTH*DI*DTR];
__device__ __align__(16) bf16 g_wdtfl[DEPTH*DI*DTR];
__device__ __align__(16) bf16 g_wdtbh[DEPTH*DI*DTR];
__device__ __align__(16) bf16 g_wdtbl[DEPTH*DI*DTR];
__device__ __align__(16) bf16 g_wpth [DM*768];
__device__ __align__(16) bf16 g_wptl [DM*768];
__device__ __align__(16) bf16 g_wc1h [DM*4608];
__device__ __align__(16) bf16 g_wc1l [DM*4608];
__device__ __align__(16) bf16 g_wc2h [DM*4608];
__device__ __align__(16) bf16 g_wc2l [DM*4608];

__device__ __forceinline__ void bsplit(float v, bf16& h, bf16& l) {
    h = __float2bfloat16(v);
    l = __float2bfloat16(v - __bfloat162float(h));
}

// ---------------------------------------------------------------------------
// mma.sync bf16 GEMM, hi/lo 3-term split, fp32 A-side with on-the-fly bsplit,
// register-staged prefetch pipeline, split-K (atomicAdd) + dual-direction.
// A fp32: a = alpha*(aF[m,k] + aF2[m,k])  (aF2 optional)
// B bf16 hi/lo pairs (pre-converted weights).
// grid = (Ntiles, Mtiles, ndir*nsplit). K % (32*nsplit) == 0.
// EPI: 0 raw, 1 +bias[n] (split0), 2 softplus(+bias[n]) [nsplit==1],
//      3 +bias[n]+pos[(m%256)*N+n] (split0)
// ---------------------------------------------------------------------------
#define MMA_BF16(d, a, b) \
    asm volatile("mma.sync.aligned.m16n8k16.row.col.f32.bf16.bf16.f32 " \
        "{%0,%1,%2,%3},{%4,%5,%6,%7},{%8,%9},{%0,%1,%2,%3};" \
        : "+f"((d)[0]), "+f"((d)[1]), "+f"((d)[2]), "+f"((d)[3]) \
        : "r"((a)[0]), "r"((a)[1]), "r"((a)[2]), "r"((a)[3]), \
          "r"((b)[0]), "r"((b)[1]))

template<int EPI>
__global__ __launch_bounds__(256)
void tgemm_kernel(const float* __restrict__ aF, const float* __restrict__ aF2,
                  float alpha, int lda,
                  const bf16* __restrict__ bH, const bf16* __restrict__ bL, int ldb,
                  float* __restrict__ C, int ldc, int M, int N, int K,
                  const float* __restrict__ bias, const float* __restrict__ pos,
                  int nsplit,
                  const float* aFd1, const float* aF2d1,
                  const bf16* bHd1, const bf16* bLd1,
                  float* Cd1, const float* biasd1)
{
    __shared__ __align__(16) bf16 AsH[128][40];
    __shared__ __align__(16) bf16 AsL[128][40];
    __shared__ __align__(16) bf16 BsH[64][40];
    __shared__ __align__(16) bf16 BsL[64][40];

    const int split = (int)blockIdx.z % nsplit;
    const int dir   = (int)blockIdx.z / nsplit;
    if (dir) { aF = aFd1; aF2 = aF2d1; bH = bHd1; bL = bLd1; C = Cd1; bias = biasd1; }

    const int tid = threadIdx.x, wid = tid >> 5, lid = tid & 31;
    const int wm = wid >> 1, wn = wid & 1;
    const int g = lid >> 2, t = lid & 3;
    const int m0 = blockIdx.y * 128, n0 = blockIdx.x * 64;
    const int Kc = K / nsplit;
    const int kbeg = split * Kc, kend = kbeg + Kc;

    // per-thread tile-load coordinates
    const int ar0 = tid >> 2, aq = tid & 3;          // A rows ar0, ar0+64
    const int br  = tid >> 2, bq = tid & 3;          // B row

    float acc[2][4][4];
    #pragma unroll
    for (int i = 0; i < 2; i++)
        #pragma unroll
        for (int j = 0; j < 4; j++)
            #pragma unroll
            for (int e = 0; e < 4; e++) acc[i][j][e] = 0.f;

    // staging registers
    float4 sa[2][2];
    uint4  sbh, sbl;

    auto load_stage = [&](int kc) {
        #pragma unroll
        for (int it = 0; it < 2; it++) {
            const int mg = m0 + ar0 + it * 64;
            if (mg < M) {
                const float* p = aF + (size_t)mg * lda + kc + aq * 8;
                float4 v0 = *(const float4*)p;
                float4 v1 = *(const float4*)(p + 4);
                if (aF2) {
                    const float* p2 = aF2 + (size_t)mg * lda + kc + aq * 8;
                    float4 w0 = *(const float4*)p2;
                    float4 w1 = *(const float4*)(p2 + 4);
                    v0.x += w0.x; v0.y += w0.y; v0.z += w0.z; v0.w += w0.w;
                    v1.x += w1.x; v1.y += w1.y; v1.z += w1.z; v1.w += w1.w;
                }
                sa[it][0] = v0; sa[it][1] = v1;
            } else {
                sa[it][0] = make_float4(0.f, 0.f, 0.f, 0.f);
                sa[it][1] = make_float4(0.f, 0.f, 0.f, 0.f);
            }
        }
        sbh = *(const uint4*)(bH + (size_t)(n0 + br) * ldb + kc + bq * 8);
        sbl = *(const uint4*)(bL + (size_t)(n0 + br) * ldb + kc + bq * 8);
    };

    auto store_stage = [&]() {
        #pragma unroll
        for (int it = 0; it < 2; it++) {
            const int row = ar0 + it * 64;
            union { bf16 b[8]; uint4 u; } Th, Tl;
            const float* fp = (const float*)&sa[it][0];
            #pragma unroll
            for (int e = 0; e < 8; e++) {
                float v = alpha * fp[e];
                bsplit(v, Th.b[e], Tl.b[e]);
            }
            *(uint4*)&AsH[row][aq * 8] = Th.u;
            *(uint4*)&AsL[row][aq * 8] = Tl.u;
        }
        *(uint4*)&BsH[br][bq * 8] = sbh;
        *(uint4*)&BsL[br][bq * 8] = sbl;
    };

    load_stage(kbeg);
    for (int kc = kbeg; kc < kend; kc += 32) {
        store_stage();
        __syncthreads();
        if (kc + 32 < kend) load_stage(kc + 32);   // prefetch overlaps compute

        #pragma unroll
        for (int kk = 0; kk < 32; kk += 16) {
            uint32_t ah[2][4], al[2][4], bh[4][2], bl[4][2];
            #pragma unroll
            for (int i = 0; i < 2; i++) {
                const int r = wm * 32 + i * 16 + g;
                ah[i][0] = *(const uint32_t*)&AsH[r    ][kk + 2 * t];
                ah[i][1] = *(const uint32_t*)&AsH[r + 8][kk + 2 * t];
                ah[i][2] = *(const uint32_t*)&AsH[r    ][kk + 2 * t + 8];
                ah[i][3] = *(const uint32_t*)&AsH[r + 8][kk + 2 * t + 8];
                al[i][0] = *(const uint32_t*)&AsL[r    ][kk + 2 * t];
                al[i][1] = *(const uint32_t*)&AsL[r + 8][kk + 2 * t];
                al[i][2] = *(const uint32_t*)&AsL[r    ][kk + 2 * t + 8];
                al[i][3] = *(const uint32_t*)&AsL[r + 8][kk + 2 * t + 8];
            }
            #pragma unroll
            for (int j = 0; j < 4; j++) {
                const int r = wn * 32 + j * 8 + g;
                bh[j][0] = *(const uint32_t*)&BsH[r][kk + 2 * t];
                bh[j][1] = *(const uint32_t*)&BsH[r][kk + 2 * t + 8];
                bl[j][0] = *(const uint32_t*)&BsL[r][kk + 2 * t];
                bl[j][1] = *(const uint32_t*)&BsL[r][kk + 2 * t + 8];
            }
            #pragma unroll
            for (int i = 0; i < 2; i++)
                #pragma unroll
                for (int j = 0; j < 4; j++) {
                    MMA_BF16(acc[i][j], ah[i], bh[j]);
                    MMA_BF16(acc[i][j], ah[i], bl[j]);
                    MMA_BF16(acc[i][j], al[i], bh[j]);
                }
        }
        __syncthreads();
    }

    const bool dobias = (split == 0);
    #pragma unroll
    for (int i = 0; i < 2; i++) {
        const int r0 = m0 + wm * 32 + i * 16 + g;
        #pragma unroll
        for (int j = 0; j < 4; j++) {
            const int c = n0 + wn * 32 + j * 8 + 2 * t;
            #pragma unroll
            for (int half = 0; half < 2; half++) {
                const int m = r0 + half * 8;
                if (m >= M) continue;
                #pragma unroll
                for (int e = 0; e < 2; e++) {
                    const int n = c + e;
                    float v = acc[i][j][half * 2 + e];
                    if (EPI == 1) { if (dobias) v += bias[n]; }
                    else if (EPI == 2) { v += bias[n]; v = (v > 20.f) ? v : log1pf(__expf(v)); }
                    else if (EPI == 3) { if (dobias) v += bias[n] + pos[(m & 255) * N + n]; }
                    float* cp = C + (size_t)m * ldc + n;
                    if (nsplit > 1) atomicAdd(cp, v);
                    else            *cp = v;
                }
            }
        }
    }
}

// ---------------------------------------------------------------------------
// Batched weight conversion: all 9 tensors in ONE launch.
// ---------------------------------------------------------------------------
struct CSeg { const float* s; bf16* h; bf16* l; unsigned nq; };  // nq = quads
struct CTab { CSeg seg[9]; };

__global__ void convert_all_kernel(CTab tab)
{
    unsigned q = blockIdx.x * 256 + threadIdx.x;
    #pragma unroll
    for (int i = 0; i < 9; i++) {
        if (q < tab.seg[i].nq) {
            const unsigned idx = q * 4;
            float4 v = *(const float4*)(tab.seg[i].s + idx);
            bf16* dh = tab.seg[i].h + idx;
            bf16* dl = tab.seg[i].l + idx;
            bsplit(v.x, dh[0], dl[0]);
            bsplit(v.y, dh[1], dl[1]);
            bsplit(v.z, dh[2], dl[2]);
            bsplit(v.w, dh[3], dl[3]);
            return;
        }
        q -= tab.seg[i].nq;
    }
}

// ---------------------------------------------------------------------------
// Elementwise
// ---------------------------------------------------------------------------
__global__ __launch_bounds__(256)
void addnorm_kernel(const float* __restrict__ xin, float* __restrict__ resid,
                    float* __restrict__ hout, const float* __restrict__ w)
{
    const int row = blockIdx.x;
    const int tid = threadIdx.x;
    const size_t base = (size_t)row * DM;
    float v0 = resid[base + tid]       + xin[base + tid];
    float v1 = resid[base + 256 + tid] + xin[base + 256 + tid];
    resid[base + tid] = v0;
    resid[base + 256 + tid] = v1;
    float s = v0 * v0 + v1 * v1;
    #pragma unroll
    for (int o = 16; o > 0; o >>= 1) s += __shfl_xor_sync(0xffffffffu, s, o);
    __shared__ float ss[8];
    __shared__ float stot;
    if ((tid & 31) == 0) ss[tid >> 5] = s;
    __syncthreads();
    if (tid == 0) {
        float tsum = 0.f;
        #pragma unroll
        for (int i = 0; i < 8; i++) tsum += ss[i];
        stot = tsum;
    }
    __syncthreads();
    const float rstd = rsqrtf(stot * (1.f / DM) + 1e-5f);
    hout[base + tid]       = v0 * rstd * w[tid];
    hout[base + 256 + tid] = v1 * rstd * w[256 + tid];
}

__global__ __launch_bounds__(256)
void dwconv_kernel(const float* __restrict__ xz,
                   const float* __restrict__ w_f, const float* __restrict__ cb_f,
                   const float* __restrict__ w_b, const float* __restrict__ cb_b,
                   float* __restrict__ out_f, float* __restrict__ out_b)
{
    int id = blockIdx.x * 256 + threadIdx.x;
    if (id >= MROWS * DI) return;
    const int dir = blockIdx.y;
    const float* w  = dir ? w_b  : w_f;
    const float* cb = dir ? cb_b : cb_f;
    float* out      = dir ? out_b : out_f;
    int d  = id & (DI - 1);
    int bl = id >> 10;
    int l  = bl & 255, b = bl >> 8;
    float4 wv = *(const float4*)(w + d * 4);
    float acc = cb[d];
    const float* base = xz + ((size_t)b * LSEQ) * (2 * DI) + d;
    if (!dir) {
        if (l >= 3) acc += wv.x * base[(size_t)(l - 3) * 2048];
        if (l >= 2) acc += wv.y * base[(size_t)(l - 2) * 2048];
        if (l >= 1) acc += wv.z * base[(size_t)(l - 1) * 2048];
        acc += wv.w * base[(size_t)l * 2048];
    } else {
        if (l + 3 < 256) acc += wv.x * base[(size_t)(l + 3) * 2048];
        if (l + 2 < 256) acc += wv.y * base[(size_t)(l + 2) * 2048];
        if (l + 1 < 256) acc += wv.z * base[(size_t)(l + 1) * 2048];
        acc += wv.w * base[(size_t)l * 2048];
    }
    out[id] = acc / (1.f + __expf(-acc));
}

__global__ void im2col_patch_kernel(const float* __restrict__ x, float* __restrict__ col)
{
    int id = blockIdx.x * 256 + threadIdx.x;
    if (id >= MROWS * 768) return;
    int k = id % 768;
    int m = id / 768;
    int b = m >> 8, l = m & 255;
    int i = l >> 4, j = l & 15;
    int ci = k >> 8, r = k & 255;
    int ki = r >> 4, kj = r & 15;
    col[id] = x[(((size_t)b * 3 + ci) * 256 + i * 16 + ki) * 256 + j * 16 + kj];
}

__global__ void im2col_head_kernel(const float* __restrict__ src, float* __restrict__ col,
                                   int H, int OH)
{
    int id = blockIdx.x * 256 + threadIdx.x;
    const int total = 8 * OH * OH * 4608;
    if (id >= total) return;
    int k = id % 4608;
    int m = id / 4608;
    int x = m % OH;
    int y = (m / OH) % OH;
    int b = m / (OH * OH);
    int ci = k / 9;
    int r = k - ci * 9;
    int dy = r / 3, dx = r - dy * 3;
    col[id] = src[(((size_t)b * H * H) + (y + dy) * H + (x + dx)) * 512 + ci];
}

__global__ __launch_bounds__(128)
void scan_kernel(const float* __restrict__ dt_f, const float* __restrict__ dt_b,
                 const float* __restrict__ u_f,  const float* __restrict__ u_b,
                 const float* __restrict__ xd_f, const float* __restrict__ xd_b,
                 const float* __restrict__ xz,
                 const float* __restrict__ Alog_f, const float* __restrict__ Alog_b,
                 const float* __restrict__ Dp_f, const float* __restrict__ Dp_b,
                 float* __restrict__ y_f, float* __restrict__ y_b)
{
    const int b = blockIdx.x, chunk = blockIdx.y, dir = blockIdx.z;
    const int tid = threadIdx.x;
    const int d = chunk * 128 + tid;

    const float* dt   = dir ? dt_b   : dt_f;
    const float* u    = dir ? u_b    : u_f;
    const float* xd   = dir ? xd_b   : xd_f;
    const float* Alog = dir ? Alog_b : Alog_f;
    const float* Dp   = dir ? Dp_b   : Dp_f;
    float*       y    = dir ? y_b    : y_f;

    float a[DS];
    bool pw = true;
    #pragma unroll
    for (int n = 0; n < DS; n++) {
        a[n] = -__expf(Alog[(size_t)d * DS + n]);
        pw = pw && (fabsf(a[n] - (float)(n + 1) * a[0]) <= 1e-4f * (float)(n + 1));
    }
    const float Dv = Dp[d];
    float h[DS];
    #pragma unroll
    for (int n = 0; n < DS; n++) h[n] = 0.f;

    __shared__ float sBC[2][32];

    const int l0 = dir ? (LSEQ - 1) : 0;
    size_t bb = (size_t)(b * LSEQ + l0);
    float dtv = dt[bb * DI + d];
    float uv  = u [bb * DI + d];
    float zv  = xz[bb * (2 * DI) + DI + d];
    if (tid < 32) sBC[0][tid] = xd[bb * 64 + 32 + tid];
    __syncthreads();

    for (int t = 0; t < LSEQ; t++) {
        const int cur = t & 1, nxt = cur ^ 1;
        const float dtc = dtv, uc = uv, zc = zv;
        const int l = dir ? (LSEQ - 1 - t) : t;
        if (t < LSEQ - 1) {
            const int l2 = dir ? (LSEQ - 2 - t) : (t + 1);
            bb = (size_t)(b * LSEQ + l2);
            dtv = dt[bb * DI + d];
            uv  = u [bb * DI + d];
            zv  = xz[bb * (2 * DI) + DI + d];
            if (tid < 32) sBC[nxt][tid] = xd[bb * 64 + 32 + tid];
        }
        const float dtu = dtc * uc;
        float yv = 0.f;
        if (pw) {
            const float e = __expf(dtc * a[0]);
            float p = 1.f;
            #pragma unroll
            for (int n = 0; n < DS; n++) {
                p *= e;
                h[n] = p * h[n] + dtu * sBC[cur][n];
                yv += h[n] * sBC[cur][16 + n];
            }
        } else {
            #pragma unroll
            for (int n = 0; n < DS; n++) {
                const float p = __expf(dtc * a[n]);
                h[n] = p * h[n] + dtu * sBC[cur][n];
                yv += h[n] * sBC[cur][16 + n];
            }
        }
        yv = (yv + Dv * uc) * (zc / (1.f + __expf(-zc)));
        y[((size_t)(b * LSEQ + l)) * DI + d] = yv;
        __syncthreads();
    }
}

__global__ void pool_kernel(const float* __restrict__ src, float* __restrict__ dst,
                            int IH, int OH)
{
    int id = blockIdx.x * 256 + threadIdx.x;
    const int total = 8 * OH * OH * 512;
    if (id >= total) return;
    int c = id & 511;
    int m = id >> 9;
    int q = m % OH;
    int p = (m / OH) % OH;
    int b = m / (OH * OH);
    int sp = p * IH / OH, ep = ((p + 1) * IH + OH - 1) / OH;
    int sq = q * IH / OH, eq = ((q + 1) * IH + OH - 1) / OH;
    float s = 0.f;
    for (int y = sp; y < ep; y++)
        for (int x = sq; x < eq; x++)
            s += src[(((size_t)b * IH * IH) + y * IH + x) * 512 + c];
    dst[id] = s / (float)((ep - sp) * (eq - sq));
}

// ---------------------------------------------------------------------------
// Host orchestration
// ---------------------------------------------------------------------------
extern "C" void kernel_launch(void* const* d_in, const int* in_sizes, int n_in,
                              void* d_out, int out_size)
{
    const float* x        = (const float*)d_in[0];
    const float* patch_w  = (const float*)d_in[1];
    const float* patch_b  = (const float*)d_in[2];
    const float* pos      = (const float*)d_in[3];
    const float* norm_w   = (const float*)d_in[4];
    const float* in_w     = (const float*)d_in[5];
    const float* cw_f     = (const float*)d_in[6];
    const float* cb_f     = (const float*)d_in[7];
    const float* xp_f     = (const float*)d_in[8];
    const float* dtw_f    = (const float*)d_in[9];
    const float* dtb_f    = (const float*)d_in[10];
    const float* al_f     = (const float*)d_in[11];
    const float* D_f      = (const float*)d_in[12];
    const float* cw_b     = (const float*)d_in[13];
    const float* cb_b     = (const float*)d_in[14];
    const float* xp_b     = (const float*)d_in[15];
    const float* dtw_b    = (const float*)d_in[16];
    const float* dtb_b    = (const float*)d_in[17];
    const float* al_b     = (const float*)d_in[18];
    const float* D_b      = (const float*)d_in[19];
    const float* out_w    = (const float*)d_in[20];
    const float* norm_fw  = (const float*)d_in[21];
    const float* c1w      = (const float*)d_in[22];
    const float* c1b      = (const float*)d_in[23];
    const float* c2w      = (const float*)d_in[24];
    const float* c2b      = (const float*)d_in[25];
    float* out = (float*)d_out;

    float *resid, *hbuf, *xbuf, *xz, *xcf, *xcb, *xd, *dtf, *dtbuf, *yf, *yb,
          *colf, *t1, *p1, *t2;
    bf16 *winh, *winl, *wouth, *woutl, *wxpfh, *wxpfl, *wxpbh, *wxpbl,
         *wdtfh, *wdtfl, *wdtbh, *wdtbl, *wpth, *wptl, *wc1h, *wc1l, *wc2h, *wc2l;

    cudaGetSymbolAddress((void**)&resid, g_resid);
    cudaGetSymbolAddress((void**)&hbuf,  g_h);
    cudaGetSymbolAddress((void**)&xbuf,  g_x);
    cudaGetSymbolAddress((void**)&xz,    g_xz);
    cudaGetSymbolAddress((void**)&xcf,   g_xc_f);
    cudaGetSymbolAddress((void**)&xcb,   g_xc_b);
    cudaGetSymbolAddress((void**)&xd,    g_xd);
    cudaGetSymbolAddress((void**)&dtf,   g_dt_f);
    cudaGetSymbolAddress((void**)&dtbuf, g_dt_b);
    cudaGetSymbolAddress((void**)&yf,    g_y_f);
    cudaGetSymbolAddress((void**)&yb,    g_y_b);
    cudaGetSymbolAddress((void**)&colf,  g_colf);
    cudaGetSymbolAddress((void**)&t1,    g_t1);
    cudaGetSymbolAddress((void**)&p1,    g_p1);
    cudaGetSymbolAddress((void**)&t2,    g_t2);
    cudaGetSymbolAddress((void**)&winh,  g_winh);
    cudaGetSymbolAddress((void**)&winl,  g_winl);
    cudaGetSymbolAddress((void**)&wouth, g_wouth);
    cudaGetSymbolAddress((void**)&woutl, g_woutl);
    cudaGetSymbolAddress((void**)&wxpfh, g_wxpfh);
    cudaGetSymbolAddress((void**)&wxpfl, g_wxpfl);
    cudaGetSymbolAddress((void**)&wxpbh, g_wxpbh);
    cudaGetSymbolAddress((void**)&wxpbl, g_wxpbl);
    cudaGetSymbolAddress((void**)&wdtfh, g_wdtfh);
    cudaGetSymbolAddress((void**)&wdtfl, g_wdtfl);
    cudaGetSymbolAddress((void**)&wdtbh, g_wdtbh);
    cudaGetSymbolAddress((void**)&wdtbl, g_wdtbl);
    cudaGetSymbolAddress((void**)&wpth,  g_wpth);
    cudaGetSymbolAddress((void**)&wptl,  g_wptl);
    cudaGetSymbolAddress((void**)&wc1h,  g_wc1h);
    cudaGetSymbolAddress((void**)&wc1l,  g_wc1l);
    cudaGetSymbolAddress((void**)&wc2h,  g_wc2h);
    cudaGetSymbolAddress((void**)&wc2l,  g_wc2l);

    float* xdf = xd;
    float* xdb = xd + (size_t)MROWS * 64;

    // ---- launch 1: ALL weight conversions batched ----
    {
        CTab tab;
        unsigned totq = 0;
        auto add = [&](int i, const float* s, bf16* h, bf16* l, unsigned n) {
            tab.seg[i] = { s, h, l, n / 4 };
            totq += n / 4;
        };
        add(0, in_w,   winh,  winl,  DEPTH * 2 * DI * DM);
        add(1, out_w,  wouth, woutl, DEPTH * DM * DI);
        add(2, xp_f,   wxpfh, wxpfl, DEPTH * 64 * DI);
        add(3, xp_b,   wxpbh, wxpbl, DEPTH * 64 * DI);
        add(4, dtw_f,  wdtfh, wdtfl, DEPTH * DI * DTR);
        add(5, dtw_b,  wdtbh, wdtbl, DEPTH * DI * DTR);
        add(6, patch_w, wpth, wptl,  DM * 768);
        add(7, c1w,    wc1h,  wc1l,  DM * 4608);
        add(8, c2w,    wc2h,  wc2l,  DM * 4608);
        convert_all_kernel<<<(totq + 255) / 256, 256>>>(tab);
    }

    cudaMemsetAsync(resid, 0, (size_t)MROWS * DM * sizeof(float));

    // ---- patch embed ----
    im2col_patch_kernel<<<(MROWS * 768 + 255) / 256, 256>>>(x, colf);
    tgemm_kernel<3><<<dim3(8, 16, 1), 256>>>(
        colf, nullptr, 1.f, 768, wpth, wptl, 768, xbuf, DM,
        MROWS, DM, 768, patch_b, pos, 1,
        nullptr, nullptr, nullptr, nullptr, nullptr, nullptr);

    // ---- 24 Mamba blocks ----
    for (int layer = 0; layer < DEPTH; ++layer) {
        addnorm_kernel<<<MROWS, 256>>>(xbuf, resid, hbuf, norm_w + (size_t)layer * DM);

        // in_proj: M=2048 N=2048 K=512 (512 CTAs) — launch #6 on first layer
        tgemm_kernel<0><<<dim3(32, 16, 1), 256>>>(
            hbuf, nullptr, 1.f, DM,
            winh + (size_t)layer * 2 * DI * DM, winl + (size_t)layer * 2 * DI * DM, DM,
            xz, 2 * DI, MROWS, 2 * DI, DM, nullptr, nullptr, 1,
            nullptr, nullptr, nullptr, nullptr, nullptr, nullptr);

        dwconv_kernel<<<dim3((MROWS * DI + 255) / 256, 2), 256>>>(
            xz, cw_f + (size_t)layer * DI * 4, cb_f + (size_t)layer * DI,
            cw_b + (size_t)layer * DI * 4, cb_b + (size_t)layer * DI, xcf, xcb);

        // x_proj both dirs, split-K=4 (128 CTAs); single memset covers both
        cudaMemsetAsync(xd, 0, (size_t)MROWS * 128 * sizeof(float));
        tgemm_kernel<0><<<dim3(1, 16, 8), 256>>>(
            xcf, nullptr, 1.f, DI,
            wxpfh + (size_t)layer * 64 * DI, wxpfl + (size_t)layer * 64 * DI, DI,
            xdf, 64, MROWS, 64, DI, nullptr, nullptr, 4,
            xcb, nullptr, wxpbh + (size_t)layer * 64 * DI, wxpbl + (size_t)layer * 64 * DI,
            xdb, nullptr);

        // dt both dirs (A = xd fp32 cols 0..31, fused split): 512 CTAs
        tgemm_kernel<2><<<dim3(16, 16, 2), 256>>>(
            xdf, nullptr, 1.f, 64,
            wdtfh + (size_t)layer * DI * DTR, wdtfl + (size_t)layer * DI * DTR, DTR,
            dtf, DI, MROWS, DI, DTR, dtb_f + (size_t)layer * DI, nullptr, 1,
            xdb, nullptr, wdtbh + (size_t)layer * DI * DTR, wdtbl + (size_t)layer * DI * DTR,
            dtbuf, dtb_b + (size_t)layer * DI);

        scan_kernel<<<dim3(BATCH, 8, 2), 128>>>(
            dtf, dtbuf, xcf, xcb, xdf, xdb, xz,
            al_f + (size_t)layer * DI * DS, al_b + (size_t)layer * DI * DS,
            D_f + (size_t)layer * DI, D_b + (size_t)layer * DI, yf, yb);

        // out_proj split-K=2, A = 0.5*(yf+yb) fused: 256 CTAs
        cudaMemsetAsync(xbuf, 0, (size_t)MROWS * DM * sizeof(float));
        tgemm_kernel<0><<<dim3(8, 16, 2), 256>>>(
            yf, yb, 0.5f, DI,
            wouth + (size_t)layer * DM * DI, woutl + (size_t)layer * DM * DI, DI,
            xbuf, DM, MROWS, DM, DI, nullptr, nullptr, 2,
            nullptr, nullptr, nullptr, nullptr, nullptr, nullptr);
    }

    // ---- final norm ----
    addnorm_kernel<<<MROWS, 256>>>(xbuf, resid, hbuf, norm_fw);

    // ---- conv1 (16->14): split-K=4 ----
    im2col_head_kernel<<<(8 * 14 * 14 * 4608 + 255) / 256, 256>>>(hbuf, colf, 16, 14);
    cudaMemsetAsync(t1, 0, (size_t)1568 * 512 * sizeof(float));
    tgemm_kernel<1><<<dim3(8, 13, 4), 256>>>(
        colf, nullptr, 1.f, 4608, wc1h, wc1l, 4608, t1, 512,
        1568, 512, 4608, c1b, nullptr, 4,
        nullptr, nullptr, nullptr, nullptr, nullptr, nullptr);
    pool_kernel<<<(8 * 8 * 8 * 512 + 255) / 256, 256>>>(t1, p1, 14, 8);

    // ---- conv2 (8->6): split-K=8 ----
    im2col_head_kernel<<<(8 * 6 * 6 * 4608 + 255) / 256, 256>>>(p1, colf, 8, 6);
    cudaMemsetAsync(t2, 0, (size_t)288 * 512 * sizeof(float));
    tgemm_kernel<1><<<dim3(8, 3, 8), 256>>>(
        colf, nullptr, 1.f, 4608, wc2h, wc2l, 4608, t2, 512,
        288, 512, 4608, c2b, nullptr, 8,
        nullptr, nullptr, nullptr, nullptr, nullptr, nullptr);
    pool_kernel<<<(8 * 4 * 4 * 512 + 255) / 256, 256>>>(t2, out, 6, 4);

    (void)in_sizes; (void)n_in; (void)out_size;
}